// round 1
// baseline (speedup 1.0000x reference)
#include <cuda_runtime.h>
#include <math.h>

#define B_  2
#define T_  2048
#define C_  768
#define NH  12
#define HD  64
#define QKV_STRIDE (3*C_)

// Scratch (allocation-free rule: __device__ globals)
__device__ float g_qkv [(size_t)B_*T_*3*C_];   // [B,T,3C] = q|k|v
__device__ float g_attn[(size_t)B_*T_*C_];     // attention output [B,T,C]

// ---------------------------------------------------------------------------
// C[M,N] = A[M,K] @ W[N,K]^T   (torch Linear layout), all row-major fp32.
// Tile 128x64, BK=16, 256 threads, 8x4 microtile.
// ---------------------------------------------------------------------------
__global__ __launch_bounds__(256) void sgemm_nt(const float* __restrict__ A,
                                                const float* __restrict__ W,
                                                float* __restrict__ Cmat,
                                                int M, int N, int K) {
    __shared__ float As[16][128];
    __shared__ float Bs[16][64];
    const int tid = threadIdx.x;
    const int tx = tid & 15, ty = tid >> 4;
    const int row0 = blockIdx.y * 128;
    const int col0 = blockIdx.x * 64;

    float acc[8][4] = {};

    for (int k0 = 0; k0 < K; k0 += 16) {
        // A tile 128x16 -> As[k][m]
        #pragma unroll
        for (int p = 0; p < 2; p++) {
            int i = tid + p * 256;
            int r = i >> 2;
            int c = (i & 3) * 4;
            float4 a = *(const float4*)&A[(size_t)(row0 + r) * K + k0 + c];
            As[c+0][r] = a.x; As[c+1][r] = a.y; As[c+2][r] = a.z; As[c+3][r] = a.w;
        }
        // W tile 64x16 -> Bs[k][n]
        {
            int r = tid >> 2;
            int c = (tid & 3) * 4;
            float4 b = *(const float4*)&W[(size_t)(col0 + r) * K + k0 + c];
            Bs[c+0][r] = b.x; Bs[c+1][r] = b.y; Bs[c+2][r] = b.z; Bs[c+3][r] = b.w;
        }
        __syncthreads();
        #pragma unroll
        for (int k = 0; k < 16; k++) {
            float4 a0 = *(const float4*)&As[k][ty*8];
            float4 a1 = *(const float4*)&As[k][ty*8+4];
            float4 b0 = *(const float4*)&Bs[k][tx*4];
            float av[8] = {a0.x,a0.y,a0.z,a0.w,a1.x,a1.y,a1.z,a1.w};
            float bv[4] = {b0.x,b0.y,b0.z,b0.w};
            #pragma unroll
            for (int i = 0; i < 8; i++)
                #pragma unroll
                for (int j = 0; j < 4; j++)
                    acc[i][j] += av[i] * bv[j];
        }
        __syncthreads();
    }
    #pragma unroll
    for (int i = 0; i < 8; i++) {
        float4 o = make_float4(acc[i][0], acc[i][1], acc[i][2], acc[i][3]);
        *(float4*)&Cmat[(size_t)(row0 + ty*8 + i) * N + col0 + tx*4] = o;
    }
}

// ---------------------------------------------------------------------------
// Flash attention, causal. One CTA per (q-block of 64, head, batch).
// KV tiles of 32 keys; online softmax; fp32 throughout.
// ---------------------------------------------------------------------------
__global__ __launch_bounds__(256) void attn_kernel(const float* __restrict__ qkv,
                                                   float* __restrict__ out) {
    __shared__ float Qs[64][64];     // [q row][dim]
    __shared__ float Kt[64][33];     // transposed: [dim][key]
    __shared__ float Vs[32][64];     // [key][dim]
    __shared__ float Ss[64][33];     // scores / probs [q row][key]
    __shared__ float m_s[64], l_s[64], a_s[64];

    const int tid = threadIdx.x;
    const int q0  = blockIdx.x * 64;
    const int h   = blockIdx.y;
    const int b   = blockIdx.z;
    const size_t base = (size_t)b * T_ * QKV_STRIDE;
    const int qcol = h * HD;
    const int kcol = C_ + h * HD;
    const int vcol = 2 * C_ + h * HD;

    // Load Q tile (64 x 64)
    #pragma unroll
    for (int p = 0; p < 4; p++) {
        int i = tid + p * 256;
        int r = i >> 4;
        int c = (i & 15) * 4;
        *(float4*)&Qs[r][c] =
            *(const float4*)&qkv[base + (size_t)(q0 + r) * QKV_STRIDE + qcol + c];
    }
    if (tid < 64) { m_s[tid] = __int_as_float(0xff800000); l_s[tid] = 0.f; }

    float o[4][4] = {};
    const int ty = tid >> 4, tx = tid & 15;   // PV / output mapping: rows ty*4, cols tx*4
    const int rb = tid >> 3, cb = tid & 7;    // S mapping (tid<128): rows rb*4, cols cb*4

    const int ntiles = q0 / 32 + 2;           // causal: only tiles with k0 <= q0+32
    __syncthreads();

    for (int kt = 0; kt < ntiles; kt++) {
        const int k0 = kt * 32;

        // Load K (transposed) and V tiles: 32 keys x 64 dims
        #pragma unroll
        for (int p = 0; p < 2; p++) {
            int i = tid + p * 256;
            int j = i >> 4;            // key 0..31
            int c = (i & 15) * 4;      // dim
            float4 kv = *(const float4*)&qkv[base + (size_t)(k0 + j) * QKV_STRIDE + kcol + c];
            Kt[c+0][j] = kv.x; Kt[c+1][j] = kv.y; Kt[c+2][j] = kv.z; Kt[c+3][j] = kv.w;
            *(float4*)&Vs[j][c] =
                *(const float4*)&qkv[base + (size_t)(k0 + j) * QKV_STRIDE + vcol + c];
        }
        __syncthreads();

        // S = (Q K^T) * scale, causal mask. 128 threads, 4x4 microtile each.
        if (tid < 128) {
            float acc[4][4] = {};
            for (int k = 0; k < 64; k += 4) {
                float4 q4[4];
                #pragma unroll
                for (int r = 0; r < 4; r++)
                    q4[r] = *(const float4*)&Qs[rb*4 + r][k];
                const float* qf = (const float*)q4;
                #pragma unroll
                for (int kk = 0; kk < 4; kk++) {
                    float kv[4];
                    #pragma unroll
                    for (int c = 0; c < 4; c++) kv[c] = Kt[k + kk][cb*4 + c];
                    #pragma unroll
                    for (int r = 0; r < 4; r++) {
                        float qv = qf[r*4 + kk];
                        #pragma unroll
                        for (int c = 0; c < 4; c++) acc[r][c] += qv * kv[c];
                    }
                }
            }
            #pragma unroll
            for (int r = 0; r < 4; r++)
                #pragma unroll
                for (int c = 0; c < 4; c++) {
                    float s = acc[r][c] * 0.125f;
                    if (k0 + cb*4 + c > q0 + rb*4 + r) s = -1e30f;
                    Ss[rb*4 + r][cb*4 + c] = s;
                }
        }
        __syncthreads();

        // Online softmax: 4 threads per row, 8 cols each.
        {
            const int row = tid >> 2;
            const int g   = tid & 3;
            float lm = -1e30f;
            #pragma unroll
            for (int j = 0; j < 8; j++) lm = fmaxf(lm, Ss[row][g*8 + j]);
            lm = fmaxf(lm, __shfl_xor_sync(0xffffffffu, lm, 1));
            lm = fmaxf(lm, __shfl_xor_sync(0xffffffffu, lm, 2));
            const float m_old = m_s[row];
            const float m_new = fmaxf(m_old, lm);
            float sum = 0.f;
            #pragma unroll
            for (int j = 0; j < 8; j++) {
                float p = __expf(Ss[row][g*8 + j] - m_new);
                Ss[row][g*8 + j] = p;
                sum += p;
            }
            sum += __shfl_xor_sync(0xffffffffu, sum, 1);
            sum += __shfl_xor_sync(0xffffffffu, sum, 2);
            if (g == 0) {
                float alpha = __expf(m_old - m_new);   // 0 on first tile
                l_s[row] = l_s[row] * alpha + sum;
                m_s[row] = m_new;
                a_s[row] = alpha;
            }
        }
        __syncthreads();

        // O = O*alpha + P @ V  (each thread: rows ty*4..+3, dims tx*4..+3)
        {
            float al[4];
            #pragma unroll
            for (int r = 0; r < 4; r++) al[r] = a_s[ty*4 + r];
            #pragma unroll
            for (int r = 0; r < 4; r++)
                #pragma unroll
                for (int c = 0; c < 4; c++) o[r][c] *= al[r];
            #pragma unroll 4
            for (int j = 0; j < 32; j++) {
                float4 v = *(const float4*)&Vs[j][tx*4];
                #pragma unroll
                for (int r = 0; r < 4; r++) {
                    float p = Ss[ty*4 + r][j];
                    o[r][0] += p * v.x; o[r][1] += p * v.y;
                    o[r][2] += p * v.z; o[r][3] += p * v.w;
                }
            }
        }
        __syncthreads();
    }

    // Normalize and write [B,T,C] (heads re-interleaved)
    #pragma unroll
    for (int r = 0; r < 4; r++) {
        float inv = 1.f / l_s[ty*4 + r];
        float4 ov = make_float4(o[r][0]*inv, o[r][1]*inv, o[r][2]*inv, o[r][3]*inv);
        *(float4*)&out[((size_t)b * T_ + q0 + ty*4 + r) * C_ + h*HD + tx*4] = ov;
    }
}

// ---------------------------------------------------------------------------
extern "C" void kernel_launch(void* const* d_in, const int* in_sizes, int n_in,
                              void* d_out, int out_size) {
    const float* x      = (const float*)d_in[0];   // [B,T,C]
    const float* W_attn = (const float*)d_in[1];   // [3C,C]
    const float* W_proj = (const float*)d_in[2];   // [C,C]
    float* out = (float*)d_out;                    // [B,T,C]

    float *qkv, *attnbuf;
    cudaGetSymbolAddress((void**)&qkv,     g_qkv);
    cudaGetSymbolAddress((void**)&attnbuf, g_attn);

    const int M = B_ * T_;  // 4096

    // 1) qkv = x @ W_attn^T   [4096 x 2304]
    sgemm_nt<<<dim3((3*C_)/64, M/128), 256>>>(x, W_attn, qkv, M, 3*C_, C_);

    // 2) causal attention -> g_attn [B,T,C]
    attn_kernel<<<dim3(T_/64, NH, B_), 256>>>(qkv, attnbuf);

    // 3) out = attn @ W_proj^T   [4096 x 768]
    sgemm_nt<<<dim3(C_/64, M/128), 256>>>(attnbuf, W_proj, out, M, C_, C_);
}

// round 3
// speedup vs baseline: 1.2706x; 1.2706x over previous
#include <cuda_runtime.h>
#include <cuda_bf16.h>
#include <cstdint>
#include <math.h>

#define B_  2
#define T_  2048
#define C_  768
#define NH  12
#define HD  64
#define QKV_STRIDE (3*C_)

// Scratch (allocation-free rule: __device__ globals)
__device__ float g_qkv [(size_t)B_*T_*3*C_];   // [B,T,3C] = q|k|v
__device__ float g_attn[(size_t)B_*T_*C_];     // attention output [B,T,C]

__device__ __forceinline__ uint32_t smem_u32(const void* p) {
    uint32_t a;
    asm("{ .reg .u64 t; cvta.to.shared.u64 t, %1; cvt.u32.u64 %0, t; }"
        : "=r"(a) : "l"(p));
    return a;
}

__device__ __forceinline__ void ldm_x4(uint32_t* r, uint32_t addr) {
    asm volatile("ldmatrix.sync.aligned.m8n8.x4.shared.b16 {%0,%1,%2,%3}, [%4];"
                 : "=r"(r[0]), "=r"(r[1]), "=r"(r[2]), "=r"(r[3]) : "r"(addr));
}

__device__ __forceinline__ void mma_bf16(float* c, const uint32_t* a, const uint32_t* b) {
    asm volatile(
        "mma.sync.aligned.m16n8k16.row.col.f32.bf16.bf16.f32 "
        "{%0,%1,%2,%3}, {%4,%5,%6,%7}, {%8,%9}, {%0,%1,%2,%3};"
        : "+f"(c[0]), "+f"(c[1]), "+f"(c[2]), "+f"(c[3])
        : "r"(a[0]), "r"(a[1]), "r"(a[2]), "r"(a[3]), "r"(b[0]), "r"(b[1]));
}

// ===========================================================================
// Tensor-core GEMM via mma.sync: C[M,N] = A[M,K] @ W[N,K]^T
// fp32 in/out, bf16 hi/lo split (3 passes -> ~fp32 precision).
// CTA tile 128x128, BK=32, 256 threads (8 warps, 2x4), 64x32 per warp.
// ===========================================================================
#define BKG 32
#define LDS_PAD 40   // 32 bf16 + 8 pad = 80B row stride (conflict-free ldmatrix)

__global__ __launch_bounds__(256) void gemm_mma(const float* __restrict__ A,
                                                const float* __restrict__ W,
                                                float* __restrict__ Cm,
                                                int M, int N, int K) {
    __shared__ __align__(16) __nv_bfloat16 As_h[128][LDS_PAD];
    __shared__ __align__(16) __nv_bfloat16 As_l[128][LDS_PAD];
    __shared__ __align__(16) __nv_bfloat16 Bs_h[128][LDS_PAD];
    __shared__ __align__(16) __nv_bfloat16 Bs_l[128][LDS_PAD];

    const int t    = threadIdx.x;
    const int lane = t & 31;
    const int wid  = t >> 5;
    const int wm   = (wid >> 2) * 64;   // warp M offset
    const int wn   = (wid & 3) * 32;    // warp N offset
    const int row0 = blockIdx.y * 128;
    const int col0 = blockIdx.x * 128;

    // per-thread load mapping: 4 float4 each for A and B tiles (128 x 32)
    const int lr = t >> 1;             // used with +64*p
    (void)lr;

    float acc[4][4][4];
    #pragma unroll
    for (int i = 0; i < 4; i++)
        #pragma unroll
        for (int j = 0; j < 4; j++)
            #pragma unroll
            for (int q = 0; q < 4; q++) acc[i][j][q] = 0.f;

    const int nchunk = K / BKG;
    float4 pa[4], pb[4];

    // ---- prefetch chunk 0 ----
    #pragma unroll
    for (int p = 0; p < 4; p++) {
        int idx = t + p * 256;
        int r = idx >> 3;
        int c = (idx & 7) << 2;
        pa[p] = *(const float4*)&A[(size_t)(row0 + r) * K + c];
        pb[p] = *(const float4*)&W[(size_t)(col0 + r) * K + c];
    }

    for (int ch = 0; ch < nchunk; ++ch) {
        // ---- store (convert) current chunk into smem ----
        #pragma unroll
        for (int p = 0; p < 4; p++) {
            int idx = t + p * 256;
            int r = idx >> 3;
            int c = (idx & 7) << 2;
            float vv[4] = {pa[p].x, pa[p].y, pa[p].z, pa[p].w};
            float wv[4] = {pb[p].x, pb[p].y, pb[p].z, pb[p].w};
            #pragma unroll
            for (int j = 0; j < 4; j++) {
                __nv_bfloat16 h = __float2bfloat16(vv[j]);
                As_h[r][c + j] = h;
                As_l[r][c + j] = __float2bfloat16(vv[j] - __bfloat162float(h));
                __nv_bfloat16 g = __float2bfloat16(wv[j]);
                Bs_h[r][c + j] = g;
                Bs_l[r][c + j] = __float2bfloat16(wv[j] - __bfloat162float(g));
            }
        }
        __syncthreads();

        // ---- prefetch next chunk (hide LDG under MMA) ----
        if (ch + 1 < nchunk) {
            const int k0 = (ch + 1) * BKG;
            #pragma unroll
            for (int p = 0; p < 4; p++) {
                int idx = t + p * 256;
                int r = idx >> 3;
                int c = (idx & 7) << 2;
                pa[p] = *(const float4*)&A[(size_t)(row0 + r) * K + k0 + c];
                pb[p] = *(const float4*)&W[(size_t)(col0 + r) * K + k0 + c];
            }
        }

        // ---- MMA over this chunk: 2 k-steps of 16 ----
        const int lrow = lane & 15;
        const int lkof = (lane >> 4) << 3;
        #pragma unroll
        for (int ks = 0; ks < 2; ks++) {
            const int kb = ks * 16 + lkof;

            uint32_t ah[4][4], al[4][4];
            #pragma unroll
            for (int mf = 0; mf < 4; mf++) {
                uint32_t aoff = (uint32_t)((wm + mf * 16 + lrow) * (LDS_PAD * 2) + kb * 2);
                ldm_x4(ah[mf], smem_u32(As_h) + aoff);
                ldm_x4(al[mf], smem_u32(As_l) + aoff);
            }
            uint32_t bh[4][2], bl[4][2];
            #pragma unroll
            for (int nn = 0; nn < 2; nn++) {
                uint32_t boff = (uint32_t)((wn + nn * 16 + lrow) * (LDS_PAD * 2) + kb * 2);
                uint32_t rh[4], rl[4];
                ldm_x4(rh, smem_u32(Bs_h) + boff);
                ldm_x4(rl, smem_u32(Bs_l) + boff);
                bh[2*nn][0] = rh[0]; bh[2*nn][1] = rh[2];
                bh[2*nn+1][0] = rh[1]; bh[2*nn+1][1] = rh[3];
                bl[2*nn][0] = rl[0]; bl[2*nn][1] = rl[2];
                bl[2*nn+1][0] = rl[1]; bl[2*nn+1][1] = rl[3];
            }

            #pragma unroll
            for (int mf = 0; mf < 4; mf++)
                #pragma unroll
                for (int nf = 0; nf < 4; nf++) {
                    mma_bf16(acc[mf][nf], ah[mf], bh[nf]);   // hi*hi
                    mma_bf16(acc[mf][nf], ah[mf], bl[nf]);   // hi*lo
                    mma_bf16(acc[mf][nf], al[mf], bh[nf]);   // lo*hi
                }
        }
        __syncthreads();
    }

    // ---- epilogue: fragments -> global ----
    #pragma unroll
    for (int mf = 0; mf < 4; mf++) {
        const int row = row0 + wm + mf * 16 + (lane >> 2);
        #pragma unroll
        for (int nf = 0; nf < 4; nf++) {
            const int col = col0 + wn + nf * 8 + (lane & 3) * 2;
            *(float2*)&Cm[(size_t)row * N + col] =
                make_float2(acc[mf][nf][0], acc[mf][nf][1]);
            *(float2*)&Cm[(size_t)(row + 8) * N + col] =
                make_float2(acc[mf][nf][2], acc[mf][nf][3]);
        }
    }
}

// ===========================================================================
// Flash attention, causal (unchanged; fp32 SIMT).
// ===========================================================================
__global__ __launch_bounds__(256) void attn_kernel(const float* __restrict__ qkv,
                                                   float* __restrict__ out) {
    __shared__ float Qs[64][64];
    __shared__ float Kt[64][33];
    __shared__ float Vs[32][64];
    __shared__ float Ss[64][33];
    __shared__ float m_s[64], l_s[64], a_s[64];

    const int tid = threadIdx.x;
    const int q0  = blockIdx.x * 64;
    const int h   = blockIdx.y;
    const int b   = blockIdx.z;
    const size_t base = (size_t)b * T_ * QKV_STRIDE;
    const int qcol = h * HD;
    const int kcol = C_ + h * HD;
    const int vcol = 2 * C_ + h * HD;

    #pragma unroll
    for (int p = 0; p < 4; p++) {
        int i = tid + p * 256;
        int r = i >> 4;
        int c = (i & 15) * 4;
        *(float4*)&Qs[r][c] =
            *(const float4*)&qkv[base + (size_t)(q0 + r) * QKV_STRIDE + qcol + c];
    }
    if (tid < 64) { m_s[tid] = __int_as_float(0xff800000); l_s[tid] = 0.f; }

    float o[4][4] = {};
    const int ty = tid >> 4, tx = tid & 15;
    const int rb = tid >> 3, cb = tid & 7;

    const int ntiles = q0 / 32 + 2;
    __syncthreads();

    for (int kt = 0; kt < ntiles; kt++) {
        const int k0 = kt * 32;

        #pragma unroll
        for (int p = 0; p < 2; p++) {
            int i = tid + p * 256;
            int j = i >> 4;
            int c = (i & 15) * 4;
            float4 kv = *(const float4*)&qkv[base + (size_t)(k0 + j) * QKV_STRIDE + kcol + c];
            Kt[c+0][j] = kv.x; Kt[c+1][j] = kv.y; Kt[c+2][j] = kv.z; Kt[c+3][j] = kv.w;
            *(float4*)&Vs[j][c] =
                *(const float4*)&qkv[base + (size_t)(k0 + j) * QKV_STRIDE + vcol + c];
        }
        __syncthreads();

        if (tid < 128) {
            float acc[4][4] = {};
            for (int k = 0; k < 64; k += 4) {
                float4 q4[4];
                #pragma unroll
                for (int r = 0; r < 4; r++)
                    q4[r] = *(const float4*)&Qs[rb*4 + r][k];
                const float* qf = (const float*)q4;
                #pragma unroll
                for (int kk = 0; kk < 4; kk++) {
                    float kv[4];
                    #pragma unroll
                    for (int c = 0; c < 4; c++) kv[c] = Kt[k + kk][cb*4 + c];
                    #pragma unroll
                    for (int r = 0; r < 4; r++) {
                        float qv = qf[r*4 + kk];
                        #pragma unroll
                        for (int c = 0; c < 4; c++) acc[r][c] += qv * kv[c];
                    }
                }
            }
            #pragma unroll
            for (int r = 0; r < 4; r++)
                #pragma unroll
                for (int c = 0; c < 4; c++) {
                    float s = acc[r][c] * 0.125f;
                    if (k0 + cb*4 + c > q0 + rb*4 + r) s = -1e30f;
                    Ss[rb*4 + r][cb*4 + c] = s;
                }
        }
        __syncthreads();

        {
            const int row = tid >> 2;
            const int g   = tid & 3;
            float lm = -1e30f;
            #pragma unroll
            for (int j = 0; j < 8; j++) lm = fmaxf(lm, Ss[row][g*8 + j]);
            lm = fmaxf(lm, __shfl_xor_sync(0xffffffffu, lm, 1));
            lm = fmaxf(lm, __shfl_xor_sync(0xffffffffu, lm, 2));
            const float m_old = m_s[row];
            const float m_new = fmaxf(m_old, lm);
            float sum = 0.f;
            #pragma unroll
            for (int j = 0; j < 8; j++) {
                float p = __expf(Ss[row][g*8 + j] - m_new);
                Ss[row][g*8 + j] = p;
                sum += p;
            }
            sum += __shfl_xor_sync(0xffffffffu, sum, 1);
            sum += __shfl_xor_sync(0xffffffffu, sum, 2);
            if (g == 0) {
                float alpha = __expf(m_old - m_new);
                l_s[row] = l_s[row] * alpha + sum;
                m_s[row] = m_new;
                a_s[row] = alpha;
            }
        }
        __syncthreads();

        {
            float al[4];
            #pragma unroll
            for (int r = 0; r < 4; r++) al[r] = a_s[ty*4 + r];
            #pragma unroll
            for (int r = 0; r < 4; r++)
                #pragma unroll
                for (int c = 0; c < 4; c++) o[r][c] *= al[r];
            #pragma unroll 4
            for (int j = 0; j < 32; j++) {
                float4 v = *(const float4*)&Vs[j][tx*4];
                #pragma unroll
                for (int r = 0; r < 4; r++) {
                    float p = Ss[ty*4 + r][j];
                    o[r][0] += p * v.x; o[r][1] += p * v.y;
                    o[r][2] += p * v.z; o[r][3] += p * v.w;
                }
            }
        }
        __syncthreads();
    }

    #pragma unroll
    for (int r = 0; r < 4; r++) {
        float inv = 1.f / l_s[ty*4 + r];
        float4 ov = make_float4(o[r][0]*inv, o[r][1]*inv, o[r][2]*inv, o[r][3]*inv);
        *(float4*)&out[((size_t)b * T_ + q0 + ty*4 + r) * C_ + h*HD + tx*4] = ov;
    }
}

// ===========================================================================
extern "C" void kernel_launch(void* const* d_in, const int* in_sizes, int n_in,
                              void* d_out, int out_size) {
    const float* x      = (const float*)d_in[0];   // [B,T,C]
    const float* W_attn = (const float*)d_in[1];   // [3C,C]
    const float* W_proj = (const float*)d_in[2];   // [C,C]
    float* out = (float*)d_out;                    // [B,T,C]

    float *qkv, *attnbuf;
    cudaGetSymbolAddress((void**)&qkv,     g_qkv);
    cudaGetSymbolAddress((void**)&attnbuf, g_attn);

    const int M = B_ * T_;  // 4096

    // 1) qkv = x @ W_attn^T   [4096 x 2304]
    gemm_mma<<<dim3((3*C_)/128, M/128), 256>>>(x, W_attn, qkv, M, 3*C_, C_);

    // 2) causal attention -> g_attn [B,T,C]
    attn_kernel<<<dim3(T_/64, NH, B_), 256>>>(qkv, attnbuf);

    // 3) out = attn @ W_proj^T   [4096 x 768]
    gemm_mma<<<dim3(C_/128, M/128), 256>>>(attnbuf, W_proj, out, M, C_, C_);
}

// round 4
// speedup vs baseline: 2.4636x; 1.9389x over previous
#include <cuda_runtime.h>
#include <cuda_bf16.h>
#include <cstdint>
#include <math.h>

#define B_  2
#define T_  2048
#define C_  768
#define NH  12
#define HD  64
#define QKV_STRIDE (3*C_)

__device__ float g_qkv [(size_t)B_*T_*3*C_];   // [B,T,3C] = q|k|v
__device__ float g_attn[(size_t)B_*T_*C_];     // attention output [B,T,C]

__device__ __forceinline__ uint32_t smem_u32(const void* p) {
    uint32_t a;
    asm("{ .reg .u64 t; cvta.to.shared.u64 t, %1; cvt.u32.u64 %0, t; }"
        : "=r"(a) : "l"(p));
    return a;
}

__device__ __forceinline__ void ldm_x4(uint32_t* r, uint32_t addr) {
    asm volatile("ldmatrix.sync.aligned.m8n8.x4.shared.b16 {%0,%1,%2,%3}, [%4];"
                 : "=r"(r[0]), "=r"(r[1]), "=r"(r[2]), "=r"(r[3]) : "r"(addr));
}
__device__ __forceinline__ void ldm_x4_t(uint32_t* r, uint32_t addr) {
    asm volatile("ldmatrix.sync.aligned.m8n8.x4.trans.shared.b16 {%0,%1,%2,%3}, [%4];"
                 : "=r"(r[0]), "=r"(r[1]), "=r"(r[2]), "=r"(r[3]) : "r"(addr));
}

__device__ __forceinline__ void mma_bf16(float* c, const uint32_t* a, const uint32_t* b) {
    asm volatile(
        "mma.sync.aligned.m16n8k16.row.col.f32.bf16.bf16.f32 "
        "{%0,%1,%2,%3}, {%4,%5,%6,%7}, {%8,%9}, {%0,%1,%2,%3};"
        : "+f"(c[0]), "+f"(c[1]), "+f"(c[2]), "+f"(c[3])
        : "r"(a[0]), "r"(a[1]), "r"(a[2]), "r"(a[3]), "r"(b[0]), "r"(b[1]));
}

__device__ __forceinline__ uint32_t pack_bf16x2(float lo, float hi) {
    __nv_bfloat162 v;
    v.x = __float2bfloat16(lo);
    v.y = __float2bfloat16(hi);
    return *(uint32_t*)&v;
}

// ===========================================================================
// GEMM via mma.sync (unchanged from round 3): C[M,N] = A[M,K] @ W[N,K]^T
// ===========================================================================
#define BKG 32
#define LDS_PAD 40

__global__ __launch_bounds__(256) void gemm_mma(const float* __restrict__ A,
                                                const float* __restrict__ W,
                                                float* __restrict__ Cm,
                                                int M, int N, int K) {
    __shared__ __align__(16) __nv_bfloat16 As_h[128][LDS_PAD];
    __shared__ __align__(16) __nv_bfloat16 As_l[128][LDS_PAD];
    __shared__ __align__(16) __nv_bfloat16 Bs_h[128][LDS_PAD];
    __shared__ __align__(16) __nv_bfloat16 Bs_l[128][LDS_PAD];

    const int t    = threadIdx.x;
    const int lane = t & 31;
    const int wid  = t >> 5;
    const int wm   = (wid >> 2) * 64;
    const int wn   = (wid & 3) * 32;
    const int row0 = blockIdx.y * 128;
    const int col0 = blockIdx.x * 128;

    float acc[4][4][4];
    #pragma unroll
    for (int i = 0; i < 4; i++)
        #pragma unroll
        for (int j = 0; j < 4; j++)
            #pragma unroll
            for (int q = 0; q < 4; q++) acc[i][j][q] = 0.f;

    const int nchunk = K / BKG;
    float4 pa[4], pb[4];

    #pragma unroll
    for (int p = 0; p < 4; p++) {
        int idx = t + p * 256;
        int r = idx >> 3;
        int c = (idx & 7) << 2;
        pa[p] = *(const float4*)&A[(size_t)(row0 + r) * K + c];
        pb[p] = *(const float4*)&W[(size_t)(col0 + r) * K + c];
    }

    for (int ch = 0; ch < nchunk; ++ch) {
        #pragma unroll
        for (int p = 0; p < 4; p++) {
            int idx = t + p * 256;
            int r = idx >> 3;
            int c = (idx & 7) << 2;
            float vv[4] = {pa[p].x, pa[p].y, pa[p].z, pa[p].w};
            float wv[4] = {pb[p].x, pb[p].y, pb[p].z, pb[p].w};
            #pragma unroll
            for (int j = 0; j < 4; j++) {
                __nv_bfloat16 h = __float2bfloat16(vv[j]);
                As_h[r][c + j] = h;
                As_l[r][c + j] = __float2bfloat16(vv[j] - __bfloat162float(h));
                __nv_bfloat16 g = __float2bfloat16(wv[j]);
                Bs_h[r][c + j] = g;
                Bs_l[r][c + j] = __float2bfloat16(wv[j] - __bfloat162float(g));
            }
        }
        __syncthreads();

        if (ch + 1 < nchunk) {
            const int k0 = (ch + 1) * BKG;
            #pragma unroll
            for (int p = 0; p < 4; p++) {
                int idx = t + p * 256;
                int r = idx >> 3;
                int c = (idx & 7) << 2;
                pa[p] = *(const float4*)&A[(size_t)(row0 + r) * K + k0 + c];
                pb[p] = *(const float4*)&W[(size_t)(col0 + r) * K + k0 + c];
            }
        }

        const int lrow = lane & 15;
        const int lkof = (lane >> 4) << 3;
        #pragma unroll
        for (int ks = 0; ks < 2; ks++) {
            const int kb = ks * 16 + lkof;

            uint32_t ah[4][4], al[4][4];
            #pragma unroll
            for (int mf = 0; mf < 4; mf++) {
                uint32_t aoff = (uint32_t)((wm + mf * 16 + lrow) * (LDS_PAD * 2) + kb * 2);
                ldm_x4(ah[mf], smem_u32(As_h) + aoff);
                ldm_x4(al[mf], smem_u32(As_l) + aoff);
            }
            uint32_t bh[4][2], bl[4][2];
            #pragma unroll
            for (int nn = 0; nn < 2; nn++) {
                uint32_t boff = (uint32_t)((wn + nn * 16 + lrow) * (LDS_PAD * 2) + kb * 2);
                uint32_t rh[4], rl[4];
                ldm_x4(rh, smem_u32(Bs_h) + boff);
                ldm_x4(rl, smem_u32(Bs_l) + boff);
                bh[2*nn][0] = rh[0]; bh[2*nn][1] = rh[2];
                bh[2*nn+1][0] = rh[1]; bh[2*nn+1][1] = rh[3];
                bl[2*nn][0] = rl[0]; bl[2*nn][1] = rl[2];
                bl[2*nn+1][0] = rl[1]; bl[2*nn+1][1] = rl[3];
            }

            #pragma unroll
            for (int mf = 0; mf < 4; mf++)
                #pragma unroll
                for (int nf = 0; nf < 4; nf++) {
                    mma_bf16(acc[mf][nf], ah[mf], bh[nf]);
                    mma_bf16(acc[mf][nf], ah[mf], bl[nf]);
                    mma_bf16(acc[mf][nf], al[mf], bh[nf]);
                }
        }
        __syncthreads();
    }

    #pragma unroll
    for (int mf = 0; mf < 4; mf++) {
        const int row = row0 + wm + mf * 16 + (lane >> 2);
        #pragma unroll
        for (int nf = 0; nf < 4; nf++) {
            const int col = col0 + wn + nf * 8 + (lane & 3) * 2;
            *(float2*)&Cm[(size_t)row * N + col] =
                make_float2(acc[mf][nf][0], acc[mf][nf][1]);
            *(float2*)&Cm[(size_t)(row + 8) * N + col] =
                make_float2(acc[mf][nf][2], acc[mf][nf][3]);
        }
    }
}

// ===========================================================================
// Flash attention, causal, tensor-core (mma.sync split-bf16).
// CTA: 128 queries x (head, batch). 8 warps; 16 q-rows per warp.
// Register softmax; K frags non-trans ldmatrix; V frags ldmatrix.trans.
// ===========================================================================
#define APAD 72          // 64 bf16 + 8 pad; row stride 144B (16B-aligned, ldm conflict-free)

__global__ __launch_bounds__(256) void attn_mma(const float* __restrict__ qkv,
                                                float* __restrict__ out) {
    __shared__ __align__(16) __nv_bfloat16 Kh[64][APAD];
    __shared__ __align__(16) __nv_bfloat16 Kl[64][APAD];
    __shared__ __align__(16) __nv_bfloat16 Vh[64][APAD];
    __shared__ __align__(16) __nv_bfloat16 Vl[64][APAD];

    const int t    = threadIdx.x;
    const int lane = t & 31;
    const int w    = t >> 5;
    const int q0   = blockIdx.x * 128;
    const int h    = blockIdx.y;
    const int b    = blockIdx.z;
    const size_t base = (size_t)b * T_ * QKV_STRIDE;
    const int qcol = h * HD;
    const int kcol = C_ + h * HD;
    const int vcol = 2 * C_ + h * HD;

    const int lrow = lane & 15;
    const int lkof = (lane >> 4) << 3;

    // ---- stage Q (128x64) into K/V buffers as bf16 hi/lo, then to registers ----
    #pragma unroll
    for (int p = 0; p < 8; p++) {
        int idx = t + p * 256;
        int r = idx >> 4;            // 0..127
        int c = (idx & 15) * 4;
        float4 v = *(const float4*)&qkv[base + (size_t)(q0 + r) * QKV_STRIDE + qcol + c];
        __nv_bfloat16* dh = (r < 64 ? &Kh[r][c] : &Vh[r - 64][c]);
        __nv_bfloat16* dl = (r < 64 ? &Kl[r][c] : &Vl[r - 64][c]);
        float vv[4] = {v.x, v.y, v.z, v.w};
        #pragma unroll
        for (int j = 0; j < 4; j++) {
            __nv_bfloat16 hi = __float2bfloat16(vv[j]);
            dh[j] = hi;
            dl[j] = __float2bfloat16(vv[j] - __bfloat162float(hi));
        }
    }
    __syncthreads();

    uint32_t qh[4][4], ql[4][4];
    {
        const uint32_t bh = (w < 4) ? smem_u32(Kh) : smem_u32(Vh);
        const uint32_t bl = (w < 4) ? smem_u32(Kl) : smem_u32(Vl);
        const uint32_t rofs = (uint32_t)(((w & 3) * 16 + lrow) * (APAD * 2));
        #pragma unroll
        for (int ks = 0; ks < 4; ks++) {
            uint32_t co = (uint32_t)((ks * 16 + lkof) * 2);
            ldm_x4(qh[ks], bh + rofs + co);
            ldm_x4(ql[ks], bl + rofs + co);
        }
    }
    __syncthreads();

    // ---- softmax state (per thread: rows rA = w*16 + lane>>2, rB = rA+8) ----
    float mA = -1e30f, mB = -1e30f, lA = 0.f, lB = 0.f;
    float oacc[8][4];
    #pragma unroll
    for (int i = 0; i < 8; i++)
        #pragma unroll
        for (int j = 0; j < 4; j++) oacc[i][j] = 0.f;

    const int rowA = q0 + w * 16 + (lane >> 2);
    const int rowmax = q0 + w * 16 + 15;
    const int ntiles = q0 / 64 + 2;

    for (int kt = 0; kt < ntiles; kt++) {
        const int k0 = kt * 64;

        // ---- cooperative load K,V tile (64x64 each) -> bf16 hi/lo smem ----
        #pragma unroll
        for (int p = 0; p < 4; p++) {
            int idx = t + p * 256;
            int r = idx >> 4;            // key 0..63
            int c = (idx & 15) * 4;
            float4 kv = *(const float4*)&qkv[base + (size_t)(k0 + r) * QKV_STRIDE + kcol + c];
            float4 vv = *(const float4*)&qkv[base + (size_t)(k0 + r) * QKV_STRIDE + vcol + c];
            float kk[4] = {kv.x, kv.y, kv.z, kv.w};
            float vw[4] = {vv.x, vv.y, vv.z, vv.w};
            #pragma unroll
            for (int j = 0; j < 4; j++) {
                __nv_bfloat16 hk = __float2bfloat16(kk[j]);
                Kh[r][c + j] = hk;
                Kl[r][c + j] = __float2bfloat16(kk[j] - __bfloat162float(hk));
                __nv_bfloat16 hv = __float2bfloat16(vw[j]);
                Vh[r][c + j] = hv;
                Vl[r][c + j] = __float2bfloat16(vw[j] - __bfloat162float(hv));
            }
        }
        __syncthreads();

        if (k0 <= rowmax) {
            // ---- S = Q K^T (split, 3 passes) ----
            float sacc[8][4];
            #pragma unroll
            for (int i = 0; i < 8; i++)
                #pragma unroll
                for (int j = 0; j < 4; j++) sacc[i][j] = 0.f;

            #pragma unroll
            for (int ks = 0; ks < 4; ks++) {
                const uint32_t co = (uint32_t)((ks * 16 + lkof) * 2);
                uint32_t kfh[8][2], kfl[8][2];
                #pragma unroll
                for (int nn = 0; nn < 4; nn++) {
                    uint32_t ro = (uint32_t)((nn * 16 + lrow) * (APAD * 2));
                    uint32_t rh[4], rl[4];
                    ldm_x4(rh, smem_u32(Kh) + ro + co);
                    ldm_x4(rl, smem_u32(Kl) + ro + co);
                    kfh[2*nn][0] = rh[0]; kfh[2*nn][1] = rh[2];
                    kfh[2*nn+1][0] = rh[1]; kfh[2*nn+1][1] = rh[3];
                    kfl[2*nn][0] = rl[0]; kfl[2*nn][1] = rl[2];
                    kfl[2*nn+1][0] = rl[1]; kfl[2*nn+1][1] = rl[3];
                }
                #pragma unroll
                for (int nf = 0; nf < 8; nf++) {
                    mma_bf16(sacc[nf], qh[ks], kfh[nf]);
                    mma_bf16(sacc[nf], qh[ks], kfl[nf]);
                    mma_bf16(sacc[nf], ql[ks], kfh[nf]);
                }
            }

            // ---- scale + causal mask ----
            const bool need_mask = (k0 + 63 > q0 + w * 16);
            #pragma unroll
            for (int nf = 0; nf < 8; nf++) {
                #pragma unroll
                for (int j = 0; j < 4; j++) sacc[nf][j] *= 0.125f;
                if (need_mask) {
                    const int col = k0 + nf * 8 + (lane & 3) * 2;
                    if (col     > rowA)     sacc[nf][0] = -1e30f;
                    if (col + 1 > rowA)     sacc[nf][1] = -1e30f;
                    if (col     > rowA + 8) sacc[nf][2] = -1e30f;
                    if (col + 1 > rowA + 8) sacc[nf][3] = -1e30f;
                }
            }

            // ---- online softmax (register, per-row over 4 lanes) ----
            float tmA = -1e30f, tmB = -1e30f;
            #pragma unroll
            for (int nf = 0; nf < 8; nf++) {
                tmA = fmaxf(tmA, fmaxf(sacc[nf][0], sacc[nf][1]));
                tmB = fmaxf(tmB, fmaxf(sacc[nf][2], sacc[nf][3]));
            }
            tmA = fmaxf(tmA, __shfl_xor_sync(0xffffffffu, tmA, 1));
            tmA = fmaxf(tmA, __shfl_xor_sync(0xffffffffu, tmA, 2));
            tmB = fmaxf(tmB, __shfl_xor_sync(0xffffffffu, tmB, 1));
            tmB = fmaxf(tmB, __shfl_xor_sync(0xffffffffu, tmB, 2));

            const float mnA = fmaxf(mA, tmA);
            const float mnB = fmaxf(mB, tmB);
            const float aA = __expf(mA - mnA);
            const float aB = __expf(mB - mnB);

            float sumA = 0.f, sumB = 0.f;
            #pragma unroll
            for (int nf = 0; nf < 8; nf++) {
                sacc[nf][0] = __expf(sacc[nf][0] - mnA);
                sacc[nf][1] = __expf(sacc[nf][1] - mnA);
                sacc[nf][2] = __expf(sacc[nf][2] - mnB);
                sacc[nf][3] = __expf(sacc[nf][3] - mnB);
                sumA += sacc[nf][0] + sacc[nf][1];
                sumB += sacc[nf][2] + sacc[nf][3];
            }
            sumA += __shfl_xor_sync(0xffffffffu, sumA, 1);
            sumA += __shfl_xor_sync(0xffffffffu, sumA, 2);
            sumB += __shfl_xor_sync(0xffffffffu, sumB, 1);
            sumB += __shfl_xor_sync(0xffffffffu, sumB, 2);

            lA = lA * aA + sumA;  mA = mnA;
            lB = lB * aB + sumB;  mB = mnB;

            #pragma unroll
            for (int nf = 0; nf < 8; nf++) {
                oacc[nf][0] *= aA; oacc[nf][1] *= aA;
                oacc[nf][2] *= aB; oacc[nf][3] *= aB;
            }

            // ---- O += P V (split P and V, 3 passes) ----
            #pragma unroll
            for (int ks = 0; ks < 4; ks++) {
                uint32_t ph[4], pl[4];
                {
                    float c0 = sacc[2*ks][0],   c1 = sacc[2*ks][1];
                    float c2 = sacc[2*ks][2],   c3 = sacc[2*ks][3];
                    float d0 = sacc[2*ks+1][0], d1 = sacc[2*ks+1][1];
                    float d2 = sacc[2*ks+1][2], d3 = sacc[2*ks+1][3];
                    ph[0] = pack_bf16x2(c0, c1);
                    ph[1] = pack_bf16x2(c2, c3);
                    ph[2] = pack_bf16x2(d0, d1);
                    ph[3] = pack_bf16x2(d2, d3);
                    __nv_bfloat162 h0 = *(__nv_bfloat162*)&ph[0];
                    __nv_bfloat162 h1 = *(__nv_bfloat162*)&ph[1];
                    __nv_bfloat162 h2 = *(__nv_bfloat162*)&ph[2];
                    __nv_bfloat162 h3 = *(__nv_bfloat162*)&ph[3];
                    pl[0] = pack_bf16x2(c0 - __bfloat162float(h0.x), c1 - __bfloat162float(h0.y));
                    pl[1] = pack_bf16x2(c2 - __bfloat162float(h1.x), c3 - __bfloat162float(h1.y));
                    pl[2] = pack_bf16x2(d0 - __bfloat162float(h2.x), d1 - __bfloat162float(h2.y));
                    pl[3] = pack_bf16x2(d2 - __bfloat162float(h3.x), d3 - __bfloat162float(h3.y));
                }
                const uint32_t krofs = (uint32_t)((ks * 16 + lrow) * (APAD * 2));
                #pragma unroll
                for (int nn = 0; nn < 4; nn++) {
                    uint32_t co = (uint32_t)((nn * 16 + lkof) * 2);
                    uint32_t vhf[4], vlf[4];
                    ldm_x4_t(vhf, smem_u32(Vh) + krofs + co);
                    ldm_x4_t(vlf, smem_u32(Vl) + krofs + co);
                    // trans pairing: frag 2nn = {r0,r1}, frag 2nn+1 = {r2,r3}
                    uint32_t b0h[2] = {vhf[0], vhf[1]};
                    uint32_t b1h[2] = {vhf[2], vhf[3]};
                    uint32_t b0l[2] = {vlf[0], vlf[1]};
                    uint32_t b1l[2] = {vlf[2], vlf[3]};
                    mma_bf16(oacc[2*nn],   ph, b0h);
                    mma_bf16(oacc[2*nn],   ph, b0l);
                    mma_bf16(oacc[2*nn],   pl, b0h);
                    mma_bf16(oacc[2*nn+1], ph, b1h);
                    mma_bf16(oacc[2*nn+1], ph, b1l);
                    mma_bf16(oacc[2*nn+1], pl, b1h);
                }
            }
        }
        __syncthreads();
    }

    // ---- epilogue: normalize and store ----
    const float invA = 1.f / lA;
    const float invB = 1.f / lB;
    const size_t orowA = ((size_t)b * T_ + rowA) * C_ + h * HD;
    #pragma unroll
    for (int nf = 0; nf < 8; nf++) {
        const int col = nf * 8 + (lane & 3) * 2;
        *(float2*)&out[orowA + col] =
            make_float2(oacc[nf][0] * invA, oacc[nf][1] * invA);
        *(float2*)&out[orowA + 8 * C_ + col] =
            make_float2(oacc[nf][2] * invB, oacc[nf][3] * invB);
    }
}

// ===========================================================================
extern "C" void kernel_launch(void* const* d_in, const int* in_sizes, int n_in,
                              void* d_out, int out_size) {
    const float* x      = (const float*)d_in[0];   // [B,T,C]
    const float* W_attn = (const float*)d_in[1];   // [3C,C]
    const float* W_proj = (const float*)d_in[2];   // [C,C]
    float* out = (float*)d_out;                    // [B,T,C]

    float *qkv, *attnbuf;
    cudaGetSymbolAddress((void**)&qkv,     g_qkv);
    cudaGetSymbolAddress((void**)&attnbuf, g_attn);

    const int M = B_ * T_;  // 4096

    gemm_mma<<<dim3((3*C_)/128, M/128), 256>>>(x, W_attn, qkv, M, 3*C_, C_);
    attn_mma<<<dim3(T_/128, NH, B_), 256>>>(qkv, attnbuf);
    gemm_mma<<<dim3(C_/128, M/128), 256>>>(attnbuf, W_proj, out, M, C_, C_);
}

// round 5
// speedup vs baseline: 2.5580x; 1.0383x over previous
#include <cuda_runtime.h>
#include <cuda_bf16.h>
#include <cstdint>
#include <math.h>

#define B_  2
#define T_  2048
#define C_  768
#define NH  12
#define HD  64
#define QKV_STRIDE (3*C_)
#define M_  (B_*T_)          // 4096

// ---------------------------------------------------------------------------
// Scratch (allocation-free rule: __device__ globals). All bf16 hi/lo planes.
// ---------------------------------------------------------------------------
__device__ __nv_bfloat16 g_xh [(size_t)M_*C_];
__device__ __nv_bfloat16 g_xl [(size_t)M_*C_];
__device__ __nv_bfloat16 g_wah[(size_t)3*C_*C_];
__device__ __nv_bfloat16 g_wal[(size_t)3*C_*C_];
__device__ __nv_bfloat16 g_wph[(size_t)C_*C_];
__device__ __nv_bfloat16 g_wpl[(size_t)C_*C_];
__device__ __nv_bfloat16 g_qh [(size_t)M_*3*C_];   // qkv hi plane [B,T,3C]
__device__ __nv_bfloat16 g_ql [(size_t)M_*3*C_];   // qkv lo plane
__device__ __nv_bfloat16 g_ah [(size_t)M_*C_];     // attn out hi
__device__ __nv_bfloat16 g_al [(size_t)M_*C_];     // attn out lo

// ---------------------------------------------------------------------------
// helpers
// ---------------------------------------------------------------------------
__device__ __forceinline__ uint32_t smem_u32(const void* p) {
    uint32_t a;
    asm("{ .reg .u64 t; cvta.to.shared.u64 t, %1; cvt.u32.u64 %0, t; }"
        : "=r"(a) : "l"(p));
    return a;
}
__device__ __forceinline__ void cp16(uint32_t dst, const void* src) {
    asm volatile("cp.async.cg.shared.global [%0], [%1], 16;" :: "r"(dst), "l"(src));
}
#define CP_COMMIT() asm volatile("cp.async.commit_group;" ::: "memory")
#define CP_WAIT0()  asm volatile("cp.async.wait_group 0;" ::: "memory")

__device__ __forceinline__ void ldm_x4(uint32_t* r, uint32_t addr) {
    asm volatile("ldmatrix.sync.aligned.m8n8.x4.shared.b16 {%0,%1,%2,%3}, [%4];"
                 : "=r"(r[0]), "=r"(r[1]), "=r"(r[2]), "=r"(r[3]) : "r"(addr));
}
__device__ __forceinline__ void ldm_x4_t(uint32_t* r, uint32_t addr) {
    asm volatile("ldmatrix.sync.aligned.m8n8.x4.trans.shared.b16 {%0,%1,%2,%3}, [%4];"
                 : "=r"(r[0]), "=r"(r[1]), "=r"(r[2]), "=r"(r[3]) : "r"(addr));
}
__device__ __forceinline__ void mma_bf16(float* c, const uint32_t* a, const uint32_t* b) {
    asm volatile(
        "mma.sync.aligned.m16n8k16.row.col.f32.bf16.bf16.f32 "
        "{%0,%1,%2,%3}, {%4,%5,%6,%7}, {%8,%9}, {%0,%1,%2,%3};"
        : "+f"(c[0]), "+f"(c[1]), "+f"(c[2]), "+f"(c[3])
        : "r"(a[0]), "r"(a[1]), "r"(a[2]), "r"(a[3]), "r"(b[0]), "r"(b[1]));
}
__device__ __forceinline__ uint32_t pack_bf16x2(float lo, float hi) {
    __nv_bfloat162 v;
    v.x = __float2bfloat16(lo);
    v.y = __float2bfloat16(hi);
    return *(uint32_t*)&v;
}

// ---------------------------------------------------------------------------
// fp32 -> bf16 hi/lo split
// ---------------------------------------------------------------------------
__global__ __launch_bounds__(256) void split_f32(const float* __restrict__ src,
                                                 __nv_bfloat16* __restrict__ h,
                                                 __nv_bfloat16* __restrict__ l,
                                                 int n4) {
    int i = blockIdx.x * 256 + threadIdx.x;
    if (i >= n4) return;
    float4 v = *(const float4*)&src[(size_t)i * 4];
    float vv[4] = {v.x, v.y, v.z, v.w};
    __nv_bfloat16 hh[4], ll[4];
    #pragma unroll
    for (int j = 0; j < 4; j++) {
        hh[j] = __float2bfloat16(vv[j]);
        ll[j] = __float2bfloat16(vv[j] - __bfloat162float(hh[j]));
    }
    *(uint2*)&h[(size_t)i * 4] = *(uint2*)hh;
    *(uint2*)&l[(size_t)i * 4] = *(uint2*)ll;
}

// ---------------------------------------------------------------------------
// GEMM on bf16 planes:  C[M,N] = (Ah+Al)[M,K] @ (Bh+Bl)[N,K]^T  (3-pass split)
// 128x128 tile, BK=32, 256 threads, cp.async double-buffered.
// OUT_BF16: write hi/lo planes; else fp32.
// ---------------------------------------------------------------------------
#define G_ROW   80                      // smem row stride bytes (32 bf16 + pad)
#define G_AH    0
#define G_AL    10240
#define G_BH    20480
#define G_BL    30720
#define G_STAGE 40960
#define G_SMEM  (2*G_STAGE)

__device__ __forceinline__ void gemm_issue(uint32_t sb,
                                           const __nv_bfloat16* Ah, const __nv_bfloat16* Al,
                                           const __nv_bfloat16* Bh, const __nv_bfloat16* Bl,
                                           int row0, int col0, int k0, int K, int t) {
    #pragma unroll
    for (int p = 0; p < 2; p++) {
        int id = t + p * 256;
        int r = id >> 2, s = id & 3;
        uint32_t d = sb + r * G_ROW + s * 16;
        size_t ga = (size_t)(row0 + r) * K + k0 + s * 8;
        size_t gb = (size_t)(col0 + r) * K + k0 + s * 8;
        cp16(d + G_AH, Ah + ga);
        cp16(d + G_AL, Al + ga);
        cp16(d + G_BH, Bh + gb);
        cp16(d + G_BL, Bl + gb);
    }
}

template<bool OUT_BF16>
__global__ __launch_bounds__(256) void gemm_planes(const __nv_bfloat16* __restrict__ Ah,
                                                   const __nv_bfloat16* __restrict__ Al,
                                                   const __nv_bfloat16* __restrict__ Bh,
                                                   const __nv_bfloat16* __restrict__ Bl,
                                                   float* __restrict__ Cf,
                                                   __nv_bfloat16* __restrict__ Ch,
                                                   __nv_bfloat16* __restrict__ Cl,
                                                   int M, int N, int K) {
    extern __shared__ __align__(16) char dyn[];
    const uint32_t sbase = smem_u32(dyn);

    const int t    = threadIdx.x;
    const int lane = t & 31;
    const int wid  = t >> 5;
    const int wm   = (wid >> 2) * 64;
    const int wn   = (wid & 3) * 32;
    const int row0 = blockIdx.y * 128;
    const int col0 = blockIdx.x * 128;
    const int lrow = lane & 15;
    const int lkof = (lane >> 4) << 3;

    float acc[4][4][4];
    #pragma unroll
    for (int i = 0; i < 4; i++)
        #pragma unroll
        for (int j = 0; j < 4; j++)
            #pragma unroll
            for (int q = 0; q < 4; q++) acc[i][j][q] = 0.f;

    const int nchunk = K / 32;

    gemm_issue(sbase, Ah, Al, Bh, Bl, row0, col0, 0, K, t);
    CP_COMMIT();

    for (int ch = 0; ch < nchunk; ++ch) {
        CP_WAIT0();
        __syncthreads();
        if (ch + 1 < nchunk) {
            gemm_issue(sbase + ((ch + 1) & 1) * G_STAGE, Ah, Al, Bh, Bl,
                       row0, col0, (ch + 1) * 32, K, t);
            CP_COMMIT();
        }
        const uint32_t sb = sbase + (ch & 1) * G_STAGE;

        #pragma unroll
        for (int ks = 0; ks < 2; ks++) {
            const int kb = ks * 16 + lkof;

            uint32_t ah[4][4], al[4][4];
            #pragma unroll
            for (int mf = 0; mf < 4; mf++) {
                uint32_t aoff = (uint32_t)((wm + mf * 16 + lrow) * G_ROW + kb * 2);
                ldm_x4(ah[mf], sb + G_AH + aoff);
                ldm_x4(al[mf], sb + G_AL + aoff);
            }
            uint32_t bh[4][2], bl[4][2];
            #pragma unroll
            for (int nn = 0; nn < 2; nn++) {
                uint32_t boff = (uint32_t)((wn + nn * 16 + lrow) * G_ROW + kb * 2);
                uint32_t rh[4], rl[4];
                ldm_x4(rh, sb + G_BH + boff);
                ldm_x4(rl, sb + G_BL + boff);
                bh[2*nn][0] = rh[0]; bh[2*nn][1] = rh[2];
                bh[2*nn+1][0] = rh[1]; bh[2*nn+1][1] = rh[3];
                bl[2*nn][0] = rl[0]; bl[2*nn][1] = rl[2];
                bl[2*nn+1][0] = rl[1]; bl[2*nn+1][1] = rl[3];
            }

            #pragma unroll
            for (int mf = 0; mf < 4; mf++)
                #pragma unroll
                for (int nf = 0; nf < 4; nf++) {
                    mma_bf16(acc[mf][nf], ah[mf], bh[nf]);
                    mma_bf16(acc[mf][nf], ah[mf], bl[nf]);
                    mma_bf16(acc[mf][nf], al[mf], bh[nf]);
                }
        }
        __syncthreads();
    }

    #pragma unroll
    for (int mf = 0; mf < 4; mf++) {
        const int row = row0 + wm + mf * 16 + (lane >> 2);
        #pragma unroll
        for (int nf = 0; nf < 4; nf++) {
            const int col = col0 + wn + nf * 8 + (lane & 3) * 2;
            if (OUT_BF16) {
                #pragma unroll
                for (int half = 0; half < 2; half++) {
                    const size_t o = (size_t)(row + half * 8) * N + col;
                    float v0 = acc[mf][nf][2*half], v1 = acc[mf][nf][2*half + 1];
                    __nv_bfloat16 h0 = __float2bfloat16(v0);
                    __nv_bfloat16 h1 = __float2bfloat16(v1);
                    __nv_bfloat162 hp; hp.x = h0; hp.y = h1;
                    __nv_bfloat162 lp;
                    lp.x = __float2bfloat16(v0 - __bfloat162float(h0));
                    lp.y = __float2bfloat16(v1 - __bfloat162float(h1));
                    *(__nv_bfloat162*)&Ch[o] = hp;
                    *(__nv_bfloat162*)&Cl[o] = lp;
                }
            } else {
                *(float2*)&Cf[(size_t)row * N + col] =
                    make_float2(acc[mf][nf][0], acc[mf][nf][1]);
                *(float2*)&Cf[(size_t)(row + 8) * N + col] =
                    make_float2(acc[mf][nf][2], acc[mf][nf][3]);
            }
        }
    }
}

// ---------------------------------------------------------------------------
// Flash attention, causal, mma.sync split-bf16, cp.async double-buffered K/V.
// CTA: 128 queries x (head,batch); 8 warps; 16 q-rows/warp; register softmax.
// ---------------------------------------------------------------------------
#define A_ROW   144                     // 64 bf16 + 8 pad
#define A_KH    0
#define A_KL    9216
#define A_VH    18432
#define A_VL    27648
#define A_STAGE 36864
#define A_SMEM  (2*A_STAGE)

__device__ __forceinline__ void attn_issue(uint32_t sb,
                                           const __nv_bfloat16* qh, const __nv_bfloat16* ql,
                                           size_t base, int k0, int kcol, int vcol, int t) {
    #pragma unroll
    for (int p = 0; p < 2; p++) {
        int id = t + p * 256;
        int r = id >> 3, s = id & 7;
        size_t gk = base + (size_t)(k0 + r) * QKV_STRIDE + kcol + s * 8;
        size_t gv = base + (size_t)(k0 + r) * QKV_STRIDE + vcol + s * 8;
        uint32_t d = sb + r * A_ROW + s * 16;
        cp16(d + A_KH, qh + gk);
        cp16(d + A_KL, ql + gk);
        cp16(d + A_VH, qh + gv);
        cp16(d + A_VL, ql + gv);
    }
}

__global__ __launch_bounds__(256) void attn_mma(const __nv_bfloat16* __restrict__ qkh,
                                                const __nv_bfloat16* __restrict__ qkl,
                                                __nv_bfloat16* __restrict__ oh,
                                                __nv_bfloat16* __restrict__ ol) {
    extern __shared__ __align__(16) char dyn[];
    const uint32_t sbase = smem_u32(dyn);

    const int t    = threadIdx.x;
    const int lane = t & 31;
    const int w    = t >> 5;
    const int q0   = blockIdx.x * 128;
    const int h    = blockIdx.y;
    const int b    = blockIdx.z;
    const size_t base = (size_t)b * T_ * QKV_STRIDE;
    const int qcol = h * HD;
    const int kcol = C_ + h * HD;
    const int vcol = 2 * C_ + h * HD;
    const int lrow = lane & 15;
    const int lkof = (lane >> 4) << 3;

    // ---- stage Q (128x64 hi/lo) into stage 0 via cp.async, frag to regs ----
    #pragma unroll
    for (int p = 0; p < 4; p++) {
        int id = t + p * 256;
        int r = id >> 3, s = id & 7;
        size_t g = base + (size_t)(q0 + r) * QKV_STRIDE + qcol + s * 8;
        uint32_t d = sbase + (r < 64 ? A_KH + r * A_ROW : A_VH + (r - 64) * A_ROW) + s * 16;
        uint32_t dl = sbase + (r < 64 ? A_KL + r * A_ROW : A_VL + (r - 64) * A_ROW) + s * 16;
        cp16(d,  qkh + g);
        cp16(dl, qkl + g);
    }
    CP_COMMIT();
    CP_WAIT0();
    __syncthreads();

    uint32_t qh[4][4], ql[4][4];
    {
        const uint32_t bh = sbase + (w < 4 ? A_KH : A_VH);
        const uint32_t bl = sbase + (w < 4 ? A_KL : A_VL);
        const uint32_t rofs = (uint32_t)(((w & 3) * 16 + lrow) * A_ROW);
        #pragma unroll
        for (int ks = 0; ks < 4; ks++) {
            uint32_t co = (uint32_t)((ks * 16 + lkof) * 2);
            ldm_x4(qh[ks], bh + rofs + co);
            ldm_x4(ql[ks], bl + rofs + co);
        }
    }
    __syncthreads();

    float mA = -1e30f, mB = -1e30f, lA = 0.f, lB = 0.f;
    float oacc[8][4];
    #pragma unroll
    for (int i = 0; i < 8; i++)
        #pragma unroll
        for (int j = 0; j < 4; j++) oacc[i][j] = 0.f;

    const int rowA = q0 + w * 16 + (lane >> 2);
    const int rowmax = q0 + w * 16 + 15;
    const int ntiles = q0 / 64 + 2;

    attn_issue(sbase, qkh, qkl, base, 0, kcol, vcol, t);
    CP_COMMIT();

    for (int kt = 0; kt < ntiles; kt++) {
        const int k0 = kt * 64;
        CP_WAIT0();
        __syncthreads();
        if (kt + 1 < ntiles) {
            attn_issue(sbase + ((kt + 1) & 1) * A_STAGE, qkh, qkl, base,
                       (kt + 1) * 64, kcol, vcol, t);
            CP_COMMIT();
        }
        const uint32_t sb = sbase + (kt & 1) * A_STAGE;

        if (k0 <= rowmax) {
            // ---- S = Q K^T ----
            float sacc[8][4];
            #pragma unroll
            for (int i = 0; i < 8; i++)
                #pragma unroll
                for (int j = 0; j < 4; j++) sacc[i][j] = 0.f;

            #pragma unroll
            for (int ks = 0; ks < 4; ks++) {
                const uint32_t co = (uint32_t)((ks * 16 + lkof) * 2);
                uint32_t kfh[8][2], kfl[8][2];
                #pragma unroll
                for (int nn = 0; nn < 4; nn++) {
                    uint32_t ro = (uint32_t)((nn * 16 + lrow) * A_ROW);
                    uint32_t rh[4], rl[4];
                    ldm_x4(rh, sb + A_KH + ro + co);
                    ldm_x4(rl, sb + A_KL + ro + co);
                    kfh[2*nn][0] = rh[0]; kfh[2*nn][1] = rh[2];
                    kfh[2*nn+1][0] = rh[1]; kfh[2*nn+1][1] = rh[3];
                    kfl[2*nn][0] = rl[0]; kfl[2*nn][1] = rl[2];
                    kfl[2*nn+1][0] = rl[1]; kfl[2*nn+1][1] = rl[3];
                }
                #pragma unroll
                for (int nf = 0; nf < 8; nf++) {
                    mma_bf16(sacc[nf], qh[ks], kfh[nf]);
                    mma_bf16(sacc[nf], qh[ks], kfl[nf]);
                    mma_bf16(sacc[nf], ql[ks], kfh[nf]);
                }
            }

            // ---- scale + causal mask ----
            const bool need_mask = (k0 + 63 > q0 + w * 16);
            #pragma unroll
            for (int nf = 0; nf < 8; nf++) {
                #pragma unroll
                for (int j = 0; j < 4; j++) sacc[nf][j] *= 0.125f;
                if (need_mask) {
                    const int col = k0 + nf * 8 + (lane & 3) * 2;
                    if (col     > rowA)     sacc[nf][0] = -1e30f;
                    if (col + 1 > rowA)     sacc[nf][1] = -1e30f;
                    if (col     > rowA + 8) sacc[nf][2] = -1e30f;
                    if (col + 1 > rowA + 8) sacc[nf][3] = -1e30f;
                }
            }

            // ---- online softmax ----
            float tmA = -1e30f, tmB = -1e30f;
            #pragma unroll
            for (int nf = 0; nf < 8; nf++) {
                tmA = fmaxf(tmA, fmaxf(sacc[nf][0], sacc[nf][1]));
                tmB = fmaxf(tmB, fmaxf(sacc[nf][2], sacc[nf][3]));
            }
            tmA = fmaxf(tmA, __shfl_xor_sync(0xffffffffu, tmA, 1));
            tmA = fmaxf(tmA, __shfl_xor_sync(0xffffffffu, tmA, 2));
            tmB = fmaxf(tmB, __shfl_xor_sync(0xffffffffu, tmB, 1));
            tmB = fmaxf(tmB, __shfl_xor_sync(0xffffffffu, tmB, 2));

            const float mnA = fmaxf(mA, tmA);
            const float mnB = fmaxf(mB, tmB);
            const float aA = __expf(mA - mnA);
            const float aB = __expf(mB - mnB);

            float sumA = 0.f, sumB = 0.f;
            #pragma unroll
            for (int nf = 0; nf < 8; nf++) {
                sacc[nf][0] = __expf(sacc[nf][0] - mnA);
                sacc[nf][1] = __expf(sacc[nf][1] - mnA);
                sacc[nf][2] = __expf(sacc[nf][2] - mnB);
                sacc[nf][3] = __expf(sacc[nf][3] - mnB);
                sumA += sacc[nf][0] + sacc[nf][1];
                sumB += sacc[nf][2] + sacc[nf][3];
            }
            sumA += __shfl_xor_sync(0xffffffffu, sumA, 1);
            sumA += __shfl_xor_sync(0xffffffffu, sumA, 2);
            sumB += __shfl_xor_sync(0xffffffffu, sumB, 1);
            sumB += __shfl_xor_sync(0xffffffffu, sumB, 2);

            lA = lA * aA + sumA;  mA = mnA;
            lB = lB * aB + sumB;  mB = mnB;

            #pragma unroll
            for (int nf = 0; nf < 8; nf++) {
                oacc[nf][0] *= aA; oacc[nf][1] *= aA;
                oacc[nf][2] *= aB; oacc[nf][3] *= aB;
            }

            // ---- O += P V ----
            #pragma unroll
            for (int ks = 0; ks < 4; ks++) {
                uint32_t ph[4], pl[4];
                {
                    float c0 = sacc[2*ks][0],   c1 = sacc[2*ks][1];
                    float c2 = sacc[2*ks][2],   c3 = sacc[2*ks][3];
                    float d0 = sacc[2*ks+1][0], d1 = sacc[2*ks+1][1];
                    float d2 = sacc[2*ks+1][2], d3 = sacc[2*ks+1][3];
                    ph[0] = pack_bf16x2(c0, c1);
                    ph[1] = pack_bf16x2(c2, c3);
                    ph[2] = pack_bf16x2(d0, d1);
                    ph[3] = pack_bf16x2(d2, d3);
                    __nv_bfloat162 h0 = *(__nv_bfloat162*)&ph[0];
                    __nv_bfloat162 h1 = *(__nv_bfloat162*)&ph[1];
                    __nv_bfloat162 h2 = *(__nv_bfloat162*)&ph[2];
                    __nv_bfloat162 h3 = *(__nv_bfloat162*)&ph[3];
                    pl[0] = pack_bf16x2(c0 - __bfloat162float(h0.x), c1 - __bfloat162float(h0.y));
                    pl[1] = pack_bf16x2(c2 - __bfloat162float(h1.x), c3 - __bfloat162float(h1.y));
                    pl[2] = pack_bf16x2(d0 - __bfloat162float(h2.x), d1 - __bfloat162float(h2.y));
                    pl[3] = pack_bf16x2(d2 - __bfloat162float(h3.x), d3 - __bfloat162float(h3.y));
                }
                const uint32_t krofs = (uint32_t)((ks * 16 + lrow) * A_ROW);
                #pragma unroll
                for (int nn = 0; nn < 4; nn++) {
                    uint32_t co = (uint32_t)((nn * 16 + lkof) * 2);
                    uint32_t vhf[4], vlf[4];
                    ldm_x4_t(vhf, sb + A_VH + krofs + co);
                    ldm_x4_t(vlf, sb + A_VL + krofs + co);
                    uint32_t b0h[2] = {vhf[0], vhf[1]};
                    uint32_t b1h[2] = {vhf[2], vhf[3]};
                    uint32_t b0l[2] = {vlf[0], vlf[1]};
                    uint32_t b1l[2] = {vlf[2], vlf[3]};
                    mma_bf16(oacc[2*nn],   ph, b0h);
                    mma_bf16(oacc[2*nn],   ph, b0l);
                    mma_bf16(oacc[2*nn],   pl, b0h);
                    mma_bf16(oacc[2*nn+1], ph, b1h);
                    mma_bf16(oacc[2*nn+1], ph, b1l);
                    mma_bf16(oacc[2*nn+1], pl, b1h);
                }
            }
        }
        __syncthreads();
    }

    // ---- epilogue: normalize and store hi/lo planes ----
    const float invA = 1.f / lA;
    const float invB = 1.f / lB;
    const size_t orowA = ((size_t)b * T_ + rowA) * C_ + h * HD;
    #pragma unroll
    for (int nf = 0; nf < 8; nf++) {
        const int col = nf * 8 + (lane & 3) * 2;
        #pragma unroll
        for (int half = 0; half < 2; half++) {
            const size_t o = orowA + half * 8 * C_ + col;
            float v0 = oacc[nf][2*half]     * (half ? invB : invA);
            float v1 = oacc[nf][2*half + 1] * (half ? invB : invA);
            __nv_bfloat16 h0 = __float2bfloat16(v0);
            __nv_bfloat16 h1 = __float2bfloat16(v1);
            __nv_bfloat162 hp; hp.x = h0; hp.y = h1;
            __nv_bfloat162 lp;
            lp.x = __float2bfloat16(v0 - __bfloat162float(h0));
            lp.y = __float2bfloat16(v1 - __bfloat162float(h1));
            *(__nv_bfloat162*)&oh[o] = hp;
            *(__nv_bfloat162*)&ol[o] = lp;
        }
    }
}

// ===========================================================================
extern "C" void kernel_launch(void* const* d_in, const int* in_sizes, int n_in,
                              void* d_out, int out_size) {
    const float* x      = (const float*)d_in[0];   // [B,T,C]
    const float* W_attn = (const float*)d_in[1];   // [3C,C]
    const float* W_proj = (const float*)d_in[2];   // [C,C]
    float* out = (float*)d_out;                    // [B,T,C]

    __nv_bfloat16 *xh, *xl, *wah, *wal, *wph, *wpl, *qh, *ql, *ah, *al;
    cudaGetSymbolAddress((void**)&xh,  g_xh);  cudaGetSymbolAddress((void**)&xl,  g_xl);
    cudaGetSymbolAddress((void**)&wah, g_wah); cudaGetSymbolAddress((void**)&wal, g_wal);
    cudaGetSymbolAddress((void**)&wph, g_wph); cudaGetSymbolAddress((void**)&wpl, g_wpl);
    cudaGetSymbolAddress((void**)&qh,  g_qh);  cudaGetSymbolAddress((void**)&ql,  g_ql);
    cudaGetSymbolAddress((void**)&ah,  g_ah);  cudaGetSymbolAddress((void**)&al,  g_al);

    cudaFuncSetAttribute(gemm_planes<true>,  cudaFuncAttributeMaxDynamicSharedMemorySize, G_SMEM);
    cudaFuncSetAttribute(gemm_planes<false>, cudaFuncAttributeMaxDynamicSharedMemorySize, G_SMEM);
    cudaFuncSetAttribute(attn_mma,           cudaFuncAttributeMaxDynamicSharedMemorySize, A_SMEM);

    // 0) conversions
    {
        int n4;
        n4 = M_ * C_ / 4;      split_f32<<<(n4 + 255) / 256, 256>>>(x,      xh,  xl,  n4);
        n4 = 3 * C_ * C_ / 4;  split_f32<<<(n4 + 255) / 256, 256>>>(W_attn, wah, wal, n4);
        n4 = C_ * C_ / 4;      split_f32<<<(n4 + 255) / 256, 256>>>(W_proj, wph, wpl, n4);
    }

    // 1) qkv = x @ W_attn^T  -> bf16 hi/lo planes
    gemm_planes<true><<<dim3((3*C_)/128, M_/128), 256, G_SMEM>>>(
        xh, xl, wah, wal, nullptr, qh, ql, M_, 3*C_, C_);

    // 2) causal attention -> hi/lo planes
    attn_mma<<<dim3(T_/128, NH, B_), 256, A_SMEM>>>(qh, ql, ah, al);

    // 3) out = attn @ W_proj^T -> fp32
    gemm_planes<false><<<dim3(C_/128, M_/128), 256, G_SMEM>>>(
        ah, al, wph, wpl, out, nullptr, nullptr, M_, C_, C_);
}

// round 6
// speedup vs baseline: 2.6072x; 1.0192x over previous
#include <cuda_runtime.h>
#include <cuda_bf16.h>
#include <cstdint>
#include <math.h>

#define B_  2
#define T_  2048
#define C_  768
#define NH  12
#define HD  64
#define QKV_STRIDE (3*C_)
#define M_  (B_*T_)          // 4096

// ---------------------------------------------------------------------------
// Scratch (allocation-free rule: __device__ globals). All bf16 hi/lo planes.
// ---------------------------------------------------------------------------
__device__ __nv_bfloat16 g_xh [(size_t)M_*C_];
__device__ __nv_bfloat16 g_xl [(size_t)M_*C_];
__device__ __nv_bfloat16 g_wah[(size_t)3*C_*C_];
__device__ __nv_bfloat16 g_wal[(size_t)3*C_*C_];
__device__ __nv_bfloat16 g_wph[(size_t)C_*C_];
__device__ __nv_bfloat16 g_wpl[(size_t)C_*C_];
__device__ __nv_bfloat16 g_qh [(size_t)M_*3*C_];   // qkv hi plane [B,T,3C]
__device__ __nv_bfloat16 g_ql [(size_t)M_*3*C_];   // qkv lo plane
__device__ __nv_bfloat16 g_ah [(size_t)M_*C_];     // attn out hi
__device__ __nv_bfloat16 g_al [(size_t)M_*C_];     // attn out lo

// ---------------------------------------------------------------------------
// helpers
// ---------------------------------------------------------------------------
__device__ __forceinline__ uint32_t smem_u32(const void* p) {
    uint32_t a;
    asm("{ .reg .u64 t; cvta.to.shared.u64 t, %1; cvt.u32.u64 %0, t; }"
        : "=r"(a) : "l"(p));
    return a;
}
__device__ __forceinline__ void cp16(uint32_t dst, const void* src) {
    asm volatile("cp.async.cg.shared.global [%0], [%1], 16;" :: "r"(dst), "l"(src));
}
#define CP_COMMIT() asm volatile("cp.async.commit_group;" ::: "memory")
#define CP_WAIT0()  asm volatile("cp.async.wait_group 0;" ::: "memory")

__device__ __forceinline__ void ldm_x4(uint32_t* r, uint32_t addr) {
    asm volatile("ldmatrix.sync.aligned.m8n8.x4.shared.b16 {%0,%1,%2,%3}, [%4];"
                 : "=r"(r[0]), "=r"(r[1]), "=r"(r[2]), "=r"(r[3]) : "r"(addr));
}
__device__ __forceinline__ void ldm_x4_t(uint32_t* r, uint32_t addr) {
    asm volatile("ldmatrix.sync.aligned.m8n8.x4.trans.shared.b16 {%0,%1,%2,%3}, [%4];"
                 : "=r"(r[0]), "=r"(r[1]), "=r"(r[2]), "=r"(r[3]) : "r"(addr));
}
__device__ __forceinline__ void mma_bf16(float* c, const uint32_t* a, const uint32_t* b) {
    asm volatile(
        "mma.sync.aligned.m16n8k16.row.col.f32.bf16.bf16.f32 "
        "{%0,%1,%2,%3}, {%4,%5,%6,%7}, {%8,%9}, {%0,%1,%2,%3};"
        : "+f"(c[0]), "+f"(c[1]), "+f"(c[2]), "+f"(c[3])
        : "r"(a[0]), "r"(a[1]), "r"(a[2]), "r"(a[3]), "r"(b[0]), "r"(b[1]));
}
__device__ __forceinline__ uint32_t pack_bf16x2(float lo, float hi) {
    __nv_bfloat162 v;
    v.x = __float2bfloat16(lo);
    v.y = __float2bfloat16(hi);
    return *(uint32_t*)&v;
}

// ---------------------------------------------------------------------------
// fp32 -> bf16 hi/lo split
// ---------------------------------------------------------------------------
__global__ __launch_bounds__(256) void split_f32(const float* __restrict__ src,
                                                 __nv_bfloat16* __restrict__ h,
                                                 __nv_bfloat16* __restrict__ l,
                                                 int n4) {
    int i = blockIdx.x * 256 + threadIdx.x;
    if (i >= n4) return;
    float4 v = *(const float4*)&src[(size_t)i * 4];
    float vv[4] = {v.x, v.y, v.z, v.w};
    __nv_bfloat16 hh[4], ll[4];
    #pragma unroll
    for (int j = 0; j < 4; j++) {
        hh[j] = __float2bfloat16(vv[j]);
        ll[j] = __float2bfloat16(vv[j] - __bfloat162float(hh[j]));
    }
    *(uint2*)&h[(size_t)i * 4] = *(uint2*)hh;
    *(uint2*)&l[(size_t)i * 4] = *(uint2*)ll;
}

// ---------------------------------------------------------------------------
// GEMM on bf16 planes:  C[M,N] = (Ah+Al)[M,K] @ (Bh+Bl)[N,K]^T  (3-pass split)
// 128x256 tile, BK=32, 512 threads (16 warps, 4x4; warp tile 32x64).
// cp.async double-buffered; one barrier per chunk.
// ---------------------------------------------------------------------------
#define G_ROW   80                      // 32 bf16 + pad (conflict-free ldmatrix)
#define G_AH    0
#define G_AL    10240                   // 128*80
#define G_BH    20480
#define G_BL    40960                   // B: 256*80 per plane
#define G_STAGE 61440
#define G_SMEM  (2*G_STAGE)

__device__ __forceinline__ void gemm_issue(uint32_t sb,
                                           const __nv_bfloat16* Ah, const __nv_bfloat16* Al,
                                           const __nv_bfloat16* Bh, const __nv_bfloat16* Bl,
                                           int row0, int col0, int k0, int K, int t) {
    // A planes: 128 rows x 4 segs = 512 -> one cp16 per thread per plane
    {
        int r = t >> 2, s = t & 3;
        uint32_t d = sb + r * G_ROW + s * 16;
        size_t ga = (size_t)(row0 + r) * K + k0 + s * 8;
        cp16(d + G_AH, Ah + ga);
        cp16(d + G_AL, Al + ga);
    }
    // B planes: 256 rows x 4 segs = 1024 -> two cp16 per thread per plane
    #pragma unroll
    for (int p = 0; p < 2; p++) {
        int id = t + p * 512;
        int r = id >> 2, s = id & 3;
        uint32_t d = sb + r * G_ROW + s * 16;
        size_t gb = (size_t)(col0 + r) * K + k0 + s * 8;
        cp16(d + G_BH, Bh + gb);
        cp16(d + G_BL, Bl + gb);
    }
}

template<bool OUT_BF16>
__global__ __launch_bounds__(512, 1) void gemm_planes(const __nv_bfloat16* __restrict__ Ah,
                                                      const __nv_bfloat16* __restrict__ Al,
                                                      const __nv_bfloat16* __restrict__ Bh,
                                                      const __nv_bfloat16* __restrict__ Bl,
                                                      float* __restrict__ Cf,
                                                      __nv_bfloat16* __restrict__ Ch,
                                                      __nv_bfloat16* __restrict__ Cl,
                                                      int M, int N, int K) {
    extern __shared__ __align__(16) char dyn[];
    const uint32_t sbase = smem_u32(dyn);

    const int t    = threadIdx.x;
    const int lane = t & 31;
    const int wid  = t >> 5;
    const int wm   = (wid >> 2) * 32;   // warp M offset (4 groups)
    const int wn   = (wid & 3) * 64;    // warp N offset (4 groups)
    const int row0 = blockIdx.y * 128;
    const int col0 = blockIdx.x * 256;
    const int lrow = lane & 15;
    const int lkof = (lane >> 4) << 3;

    float acc[2][8][4];
    #pragma unroll
    for (int i = 0; i < 2; i++)
        #pragma unroll
        for (int j = 0; j < 8; j++)
            #pragma unroll
            for (int q = 0; q < 4; q++) acc[i][j][q] = 0.f;

    const int nchunk = K / 32;

    gemm_issue(sbase, Ah, Al, Bh, Bl, row0, col0, 0, K, t);
    CP_COMMIT();

    for (int ch = 0; ch < nchunk; ++ch) {
        CP_WAIT0();
        __syncthreads();
        if (ch + 1 < nchunk) {
            gemm_issue(sbase + ((ch + 1) & 1) * G_STAGE, Ah, Al, Bh, Bl,
                       row0, col0, (ch + 1) * 32, K, t);
            CP_COMMIT();
        }
        const uint32_t sb = sbase + (ch & 1) * G_STAGE;

        #pragma unroll
        for (int ks = 0; ks < 2; ks++) {
            const int kb = ks * 16 + lkof;

            uint32_t ah[2][4], al[2][4];
            #pragma unroll
            for (int mf = 0; mf < 2; mf++) {
                uint32_t aoff = (uint32_t)((wm + mf * 16 + lrow) * G_ROW + kb * 2);
                ldm_x4(ah[mf], sb + G_AH + aoff);
                ldm_x4(al[mf], sb + G_AL + aoff);
            }
            #pragma unroll
            for (int nn = 0; nn < 4; nn++) {
                uint32_t boff = (uint32_t)((wn + nn * 16 + lrow) * G_ROW + kb * 2);
                uint32_t rh[4], rl[4];
                ldm_x4(rh, sb + G_BH + boff);
                ldm_x4(rl, sb + G_BL + boff);
                uint32_t b0h[2] = {rh[0], rh[2]};
                uint32_t b1h[2] = {rh[1], rh[3]};
                uint32_t b0l[2] = {rl[0], rl[2]};
                uint32_t b1l[2] = {rl[1], rl[3]};
                #pragma unroll
                for (int mf = 0; mf < 2; mf++) {
                    mma_bf16(acc[mf][2*nn],   ah[mf], b0h);
                    mma_bf16(acc[mf][2*nn],   ah[mf], b0l);
                    mma_bf16(acc[mf][2*nn],   al[mf], b0h);
                    mma_bf16(acc[mf][2*nn+1], ah[mf], b1h);
                    mma_bf16(acc[mf][2*nn+1], ah[mf], b1l);
                    mma_bf16(acc[mf][2*nn+1], al[mf], b1h);
                }
            }
        }
        // NOTE: no bottom barrier — stage (ch&1) is only rewritten at ch+2's
        // gemm_issue, which every thread reaches only after ch+1's top barrier,
        // i.e. after all warps finished reading this stage.
    }

    #pragma unroll
    for (int mf = 0; mf < 2; mf++) {
        const int row = row0 + wm + mf * 16 + (lane >> 2);
        #pragma unroll
        for (int nf = 0; nf < 8; nf++) {
            const int col = col0 + wn + nf * 8 + (lane & 3) * 2;
            if (OUT_BF16) {
                #pragma unroll
                for (int half = 0; half < 2; half++) {
                    const size_t o = (size_t)(row + half * 8) * N + col;
                    float v0 = acc[mf][nf][2*half], v1 = acc[mf][nf][2*half + 1];
                    __nv_bfloat16 h0 = __float2bfloat16(v0);
                    __nv_bfloat16 h1 = __float2bfloat16(v1);
                    __nv_bfloat162 hp; hp.x = h0; hp.y = h1;
                    __nv_bfloat162 lp;
                    lp.x = __float2bfloat16(v0 - __bfloat162float(h0));
                    lp.y = __float2bfloat16(v1 - __bfloat162float(h1));
                    *(__nv_bfloat162*)&Ch[o] = hp;
                    *(__nv_bfloat162*)&Cl[o] = lp;
                }
            } else {
                *(float2*)&Cf[(size_t)row * N + col] =
                    make_float2(acc[mf][nf][0], acc[mf][nf][1]);
                *(float2*)&Cf[(size_t)(row + 8) * N + col] =
                    make_float2(acc[mf][nf][2], acc[mf][nf][3]);
            }
        }
    }
}

// ---------------------------------------------------------------------------
// Flash attention, causal, mma.sync split-bf16, cp.async double-buffered K/V.
// CTA: 128 queries x (head,batch); 8 warps; 16 q-rows/warp; register softmax.
// Heavy q-blocks scheduled first (reversed blockIdx.x) for load balance.
// ---------------------------------------------------------------------------
#define A_ROW   144                     // 64 bf16 + 8 pad
#define A_KH    0
#define A_KL    9216
#define A_VH    18432
#define A_VL    27648
#define A_STAGE 36864
#define A_SMEM  (2*A_STAGE)

__device__ __forceinline__ void attn_issue(uint32_t sb,
                                           const __nv_bfloat16* qh, const __nv_bfloat16* ql,
                                           size_t base, int k0, int kcol, int vcol, int t) {
    #pragma unroll
    for (int p = 0; p < 2; p++) {
        int id = t + p * 256;
        int r = id >> 3, s = id & 7;
        size_t gk = base + (size_t)(k0 + r) * QKV_STRIDE + kcol + s * 8;
        size_t gv = base + (size_t)(k0 + r) * QKV_STRIDE + vcol + s * 8;
        uint32_t d = sb + r * A_ROW + s * 16;
        cp16(d + A_KH, qh + gk);
        cp16(d + A_KL, ql + gk);
        cp16(d + A_VH, qh + gv);
        cp16(d + A_VL, ql + gv);
    }
}

__global__ __launch_bounds__(256) void attn_mma(const __nv_bfloat16* __restrict__ qkh,
                                                const __nv_bfloat16* __restrict__ qkl,
                                                __nv_bfloat16* __restrict__ oh,
                                                __nv_bfloat16* __restrict__ ol) {
    extern __shared__ __align__(16) char dyn[];
    const uint32_t sbase = smem_u32(dyn);

    const int t    = threadIdx.x;
    const int lane = t & 31;
    const int w    = t >> 5;
    const int q0   = (gridDim.x - 1 - blockIdx.x) * 128;   // heavy blocks first
    const int h    = blockIdx.y;
    const int b    = blockIdx.z;
    const size_t base = (size_t)b * T_ * QKV_STRIDE;
    const int qcol = h * HD;
    const int kcol = C_ + h * HD;
    const int vcol = 2 * C_ + h * HD;
    const int lrow = lane & 15;
    const int lkof = (lane >> 4) << 3;

    // ---- stage Q (128x64 hi/lo) into stage 0 via cp.async, frag to regs ----
    #pragma unroll
    for (int p = 0; p < 4; p++) {
        int id = t + p * 256;
        int r = id >> 3, s = id & 7;
        size_t g = base + (size_t)(q0 + r) * QKV_STRIDE + qcol + s * 8;
        uint32_t d  = sbase + (r < 64 ? A_KH + r * A_ROW : A_VH + (r - 64) * A_ROW) + s * 16;
        uint32_t dl = sbase + (r < 64 ? A_KL + r * A_ROW : A_VL + (r - 64) * A_ROW) + s * 16;
        cp16(d,  qkh + g);
        cp16(dl, qkl + g);
    }
    CP_COMMIT();
    CP_WAIT0();
    __syncthreads();

    uint32_t qh[4][4], ql[4][4];
    {
        const uint32_t bh = sbase + (w < 4 ? A_KH : A_VH);
        const uint32_t bl = sbase + (w < 4 ? A_KL : A_VL);
        const uint32_t rofs = (uint32_t)(((w & 3) * 16 + lrow) * A_ROW);
        #pragma unroll
        for (int ks = 0; ks < 4; ks++) {
            uint32_t co = (uint32_t)((ks * 16 + lkof) * 2);
            ldm_x4(qh[ks], bh + rofs + co);
            ldm_x4(ql[ks], bl + rofs + co);
        }
    }
    __syncthreads();

    float mA = -1e30f, mB = -1e30f, lA = 0.f, lB = 0.f;
    float oacc[8][4];
    #pragma unroll
    for (int i = 0; i < 8; i++)
        #pragma unroll
        for (int j = 0; j < 4; j++) oacc[i][j] = 0.f;

    const int rowA = q0 + w * 16 + (lane >> 2);
    const int rowmax = q0 + w * 16 + 15;
    const int ntiles = q0 / 64 + 2;

    attn_issue(sbase, qkh, qkl, base, 0, kcol, vcol, t);
    CP_COMMIT();

    for (int kt = 0; kt < ntiles; kt++) {
        const int k0 = kt * 64;
        CP_WAIT0();
        __syncthreads();
        if (kt + 1 < ntiles) {
            attn_issue(sbase + ((kt + 1) & 1) * A_STAGE, qkh, qkl, base,
                       (kt + 1) * 64, kcol, vcol, t);
            CP_COMMIT();
        }
        const uint32_t sb = sbase + (kt & 1) * A_STAGE;

        if (k0 <= rowmax) {
            // ---- S = Q K^T ----
            float sacc[8][4];
            #pragma unroll
            for (int i = 0; i < 8; i++)
                #pragma unroll
                for (int j = 0; j < 4; j++) sacc[i][j] = 0.f;

            #pragma unroll
            for (int ks = 0; ks < 4; ks++) {
                const uint32_t co = (uint32_t)((ks * 16 + lkof) * 2);
                #pragma unroll
                for (int nn = 0; nn < 4; nn++) {
                    uint32_t ro = (uint32_t)((nn * 16 + lrow) * A_ROW);
                    uint32_t rh[4], rl[4];
                    ldm_x4(rh, sb + A_KH + ro + co);
                    ldm_x4(rl, sb + A_KL + ro + co);
                    uint32_t k0h[2] = {rh[0], rh[2]};
                    uint32_t k1h[2] = {rh[1], rh[3]};
                    uint32_t k0l[2] = {rl[0], rl[2]};
                    uint32_t k1l[2] = {rl[1], rl[3]};
                    mma_bf16(sacc[2*nn],   qh[ks], k0h);
                    mma_bf16(sacc[2*nn],   qh[ks], k0l);
                    mma_bf16(sacc[2*nn],   ql[ks], k0h);
                    mma_bf16(sacc[2*nn+1], qh[ks], k1h);
                    mma_bf16(sacc[2*nn+1], qh[ks], k1l);
                    mma_bf16(sacc[2*nn+1], ql[ks], k1h);
                }
            }

            // ---- scale + causal mask ----
            const bool need_mask = (k0 + 63 > q0 + w * 16);
            #pragma unroll
            for (int nf = 0; nf < 8; nf++) {
                #pragma unroll
                for (int j = 0; j < 4; j++) sacc[nf][j] *= 0.125f;
                if (need_mask) {
                    const int col = k0 + nf * 8 + (lane & 3) * 2;
                    if (col     > rowA)     sacc[nf][0] = -1e30f;
                    if (col + 1 > rowA)     sacc[nf][1] = -1e30f;
                    if (col     > rowA + 8) sacc[nf][2] = -1e30f;
                    if (col + 1 > rowA + 8) sacc[nf][3] = -1e30f;
                }
            }

            // ---- online softmax ----
            float tmA = -1e30f, tmB = -1e30f;
            #pragma unroll
            for (int nf = 0; nf < 8; nf++) {
                tmA = fmaxf(tmA, fmaxf(sacc[nf][0], sacc[nf][1]));
                tmB = fmaxf(tmB, fmaxf(sacc[nf][2], sacc[nf][3]));
            }
            tmA = fmaxf(tmA, __shfl_xor_sync(0xffffffffu, tmA, 1));
            tmA = fmaxf(tmA, __shfl_xor_sync(0xffffffffu, tmA, 2));
            tmB = fmaxf(tmB, __shfl_xor_sync(0xffffffffu, tmB, 1));
            tmB = fmaxf(tmB, __shfl_xor_sync(0xffffffffu, tmB, 2));

            const float mnA = fmaxf(mA, tmA);
            const float mnB = fmaxf(mB, tmB);
            const float aA = __expf(mA - mnA);
            const float aB = __expf(mB - mnB);

            float sumA = 0.f, sumB = 0.f;
            #pragma unroll
            for (int nf = 0; nf < 8; nf++) {
                sacc[nf][0] = __expf(sacc[nf][0] - mnA);
                sacc[nf][1] = __expf(sacc[nf][1] - mnA);
                sacc[nf][2] = __expf(sacc[nf][2] - mnB);
                sacc[nf][3] = __expf(sacc[nf][3] - mnB);
                sumA += sacc[nf][0] + sacc[nf][1];
                sumB += sacc[nf][2] + sacc[nf][3];
            }
            sumA += __shfl_xor_sync(0xffffffffu, sumA, 1);
            sumA += __shfl_xor_sync(0xffffffffu, sumA, 2);
            sumB += __shfl_xor_sync(0xffffffffu, sumB, 1);
            sumB += __shfl_xor_sync(0xffffffffu, sumB, 2);

            lA = lA * aA + sumA;  mA = mnA;
            lB = lB * aB + sumB;  mB = mnB;

            #pragma unroll
            for (int nf = 0; nf < 8; nf++) {
                oacc[nf][0] *= aA; oacc[nf][1] *= aA;
                oacc[nf][2] *= aB; oacc[nf][3] *= aB;
            }

            // ---- O += P V ----
            #pragma unroll
            for (int ks = 0; ks < 4; ks++) {
                uint32_t ph[4], pl[4];
                {
                    float c0 = sacc[2*ks][0],   c1 = sacc[2*ks][1];
                    float c2 = sacc[2*ks][2],   c3 = sacc[2*ks][3];
                    float d0 = sacc[2*ks+1][0], d1 = sacc[2*ks+1][1];
                    float d2 = sacc[2*ks+1][2], d3 = sacc[2*ks+1][3];
                    ph[0] = pack_bf16x2(c0, c1);
                    ph[1] = pack_bf16x2(c2, c3);
                    ph[2] = pack_bf16x2(d0, d1);
                    ph[3] = pack_bf16x2(d2, d3);
                    __nv_bfloat162 h0 = *(__nv_bfloat162*)&ph[0];
                    __nv_bfloat162 h1 = *(__nv_bfloat162*)&ph[1];
                    __nv_bfloat162 h2 = *(__nv_bfloat162*)&ph[2];
                    __nv_bfloat162 h3 = *(__nv_bfloat162*)&ph[3];
                    pl[0] = pack_bf16x2(c0 - __bfloat162float(h0.x), c1 - __bfloat162float(h0.y));
                    pl[1] = pack_bf16x2(c2 - __bfloat162float(h1.x), c3 - __bfloat162float(h1.y));
                    pl[2] = pack_bf16x2(d0 - __bfloat162float(h2.x), d1 - __bfloat162float(h2.y));
                    pl[3] = pack_bf16x2(d2 - __bfloat162float(h3.x), d3 - __bfloat162float(h3.y));
                }
                const uint32_t krofs = (uint32_t)((ks * 16 + lrow) * A_ROW);
                #pragma unroll
                for (int nn = 0; nn < 4; nn++) {
                    uint32_t co = (uint32_t)((nn * 16 + lkof) * 2);
                    uint32_t vhf[4], vlf[4];
                    ldm_x4_t(vhf, sb + A_VH + krofs + co);
                    ldm_x4_t(vlf, sb + A_VL + krofs + co);
                    uint32_t b0h[2] = {vhf[0], vhf[1]};
                    uint32_t b1h[2] = {vhf[2], vhf[3]};
                    uint32_t b0l[2] = {vlf[0], vlf[1]};
                    uint32_t b1l[2] = {vlf[2], vlf[3]};
                    mma_bf16(oacc[2*nn],   ph, b0h);
                    mma_bf16(oacc[2*nn],   ph, b0l);
                    mma_bf16(oacc[2*nn],   pl, b0h);
                    mma_bf16(oacc[2*nn+1], ph, b1h);
                    mma_bf16(oacc[2*nn+1], ph, b1l);
                    mma_bf16(oacc[2*nn+1], pl, b1h);
                }
            }
        }
        // no bottom barrier (same stage-reuse argument as the GEMM)
    }

    // ---- epilogue: normalize and store hi/lo planes ----
    const float invA = 1.f / lA;
    const float invB = 1.f / lB;
    const size_t orowA = ((size_t)b * T_ + rowA) * C_ + h * HD;
    #pragma unroll
    for (int nf = 0; nf < 8; nf++) {
        const int col = nf * 8 + (lane & 3) * 2;
        #pragma unroll
        for (int half = 0; half < 2; half++) {
            const size_t o = orowA + half * 8 * C_ + col;
            float v0 = oacc[nf][2*half]     * (half ? invB : invA);
            float v1 = oacc[nf][2*half + 1] * (half ? invB : invA);
            __nv_bfloat16 h0 = __float2bfloat16(v0);
            __nv_bfloat16 h1 = __float2bfloat16(v1);
            __nv_bfloat162 hp; hp.x = h0; hp.y = h1;
            __nv_bfloat162 lp;
            lp.x = __float2bfloat16(v0 - __bfloat162float(h0));
            lp.y = __float2bfloat16(v1 - __bfloat162float(h1));
            *(__nv_bfloat162*)&oh[o] = hp;
            *(__nv_bfloat162*)&ol[o] = lp;
        }
    }
}

// ===========================================================================
extern "C" void kernel_launch(void* const* d_in, const int* in_sizes, int n_in,
                              void* d_out, int out_size) {
    const float* x      = (const float*)d_in[0];   // [B,T,C]
    const float* W_attn = (const float*)d_in[1];   // [3C,C]
    const float* W_proj = (const float*)d_in[2];   // [C,C]
    float* out = (float*)d_out;                    // [B,T,C]

    __nv_bfloat16 *xh, *xl, *wah, *wal, *wph, *wpl, *qh, *ql, *ah, *al;
    cudaGetSymbolAddress((void**)&xh,  g_xh);  cudaGetSymbolAddress((void**)&xl,  g_xl);
    cudaGetSymbolAddress((void**)&wah, g_wah); cudaGetSymbolAddress((void**)&wal, g_wal);
    cudaGetSymbolAddress((void**)&wph, g_wph); cudaGetSymbolAddress((void**)&wpl, g_wpl);
    cudaGetSymbolAddress((void**)&qh,  g_qh);  cudaGetSymbolAddress((void**)&ql,  g_ql);
    cudaGetSymbolAddress((void**)&ah,  g_ah);  cudaGetSymbolAddress((void**)&al,  g_al);

    cudaFuncSetAttribute(gemm_planes<true>,  cudaFuncAttributeMaxDynamicSharedMemorySize, G_SMEM);
    cudaFuncSetAttribute(gemm_planes<false>, cudaFuncAttributeMaxDynamicSharedMemorySize, G_SMEM);
    cudaFuncSetAttribute(attn_mma,           cudaFuncAttributeMaxDynamicSharedMemorySize, A_SMEM);

    // 0) conversions
    {
        int n4;
        n4 = M_ * C_ / 4;      split_f32<<<(n4 + 255) / 256, 256>>>(x,      xh,  xl,  n4);
        n4 = 3 * C_ * C_ / 4;  split_f32<<<(n4 + 255) / 256, 256>>>(W_attn, wah, wal, n4);
        n4 = C_ * C_ / 4;      split_f32<<<(n4 + 255) / 256, 256>>>(W_proj, wph, wpl, n4);
    }

    // 1) qkv = x @ W_attn^T  -> bf16 hi/lo planes   [4096 x 2304]
    gemm_planes<true><<<dim3((3*C_)/256, M_/128), 512, G_SMEM>>>(
        xh, xl, wah, wal, nullptr, qh, ql, M_, 3*C_, C_);

    // 2) causal attention -> hi/lo planes
    attn_mma<<<dim3(T_/128, NH, B_), 256, A_SMEM>>>(qh, ql, ah, al);

    // 3) out = attn @ W_proj^T -> fp32   [4096 x 768]
    gemm_planes<false><<<dim3(C_/256, M_/128), 512, G_SMEM>>>(
        ah, al, wph, wpl, out, nullptr, nullptr, M_, C_, C_);
}

// round 7
// speedup vs baseline: 3.5124x; 1.3472x over previous
#include <cuda_runtime.h>
#include <cuda_bf16.h>
#include <cuda_fp16.h>
#include <cstdint>
#include <math.h>

#define B_  2
#define T_  2048
#define C_  768
#define NH  12
#define HD  64
#define QKV_STRIDE (3*C_)
#define M_  (B_*T_)          // 4096

// ---------------------------------------------------------------------------
// Scratch (allocation-free rule: __device__ globals).
// ---------------------------------------------------------------------------
__device__ __nv_bfloat16 g_xh [(size_t)M_*C_];
__device__ __nv_bfloat16 g_xl [(size_t)M_*C_];
__device__ __nv_bfloat16 g_wah[(size_t)3*C_*C_];
__device__ __nv_bfloat16 g_wal[(size_t)3*C_*C_];
__device__ __nv_bfloat16 g_wph[(size_t)C_*C_];
__device__ __nv_bfloat16 g_wpl[(size_t)C_*C_];
__device__ __half        g_qf [(size_t)M_*3*C_];   // qkv fp16 single plane
__device__ __nv_bfloat16 g_ah [(size_t)M_*C_];     // attn out hi (bf16)
__device__ __nv_bfloat16 g_al [(size_t)M_*C_];     // attn out lo (bf16)

// ---------------------------------------------------------------------------
// helpers
// ---------------------------------------------------------------------------
__device__ __forceinline__ uint32_t smem_u32(const void* p) {
    uint32_t a;
    asm("{ .reg .u64 t; cvta.to.shared.u64 t, %1; cvt.u32.u64 %0, t; }"
        : "=r"(a) : "l"(p));
    return a;
}
__device__ __forceinline__ void cp16(uint32_t dst, const void* src) {
    asm volatile("cp.async.cg.shared.global [%0], [%1], 16;" :: "r"(dst), "l"(src));
}
#define CP_COMMIT() asm volatile("cp.async.commit_group;" ::: "memory")
#define CP_WAIT0()  asm volatile("cp.async.wait_group 0;" ::: "memory")
#define CP_WAIT1()  asm volatile("cp.async.wait_group 1;" ::: "memory")

__device__ __forceinline__ void ldm_x4(uint32_t* r, uint32_t addr) {
    asm volatile("ldmatrix.sync.aligned.m8n8.x4.shared.b16 {%0,%1,%2,%3}, [%4];"
                 : "=r"(r[0]), "=r"(r[1]), "=r"(r[2]), "=r"(r[3]) : "r"(addr));
}
__device__ __forceinline__ void ldm_x4_t(uint32_t* r, uint32_t addr) {
    asm volatile("ldmatrix.sync.aligned.m8n8.x4.trans.shared.b16 {%0,%1,%2,%3}, [%4];"
                 : "=r"(r[0]), "=r"(r[1]), "=r"(r[2]), "=r"(r[3]) : "r"(addr));
}
__device__ __forceinline__ void mma_bf16(float* c, const uint32_t* a, const uint32_t* b) {
    asm volatile(
        "mma.sync.aligned.m16n8k16.row.col.f32.bf16.bf16.f32 "
        "{%0,%1,%2,%3}, {%4,%5,%6,%7}, {%8,%9}, {%0,%1,%2,%3};"
        : "+f"(c[0]), "+f"(c[1]), "+f"(c[2]), "+f"(c[3])
        : "r"(a[0]), "r"(a[1]), "r"(a[2]), "r"(a[3]), "r"(b[0]), "r"(b[1]));
}
__device__ __forceinline__ void mma_f16(float* c, const uint32_t* a, const uint32_t* b) {
    asm volatile(
        "mma.sync.aligned.m16n8k16.row.col.f32.f16.f16.f32 "
        "{%0,%1,%2,%3}, {%4,%5,%6,%7}, {%8,%9}, {%0,%1,%2,%3};"
        : "+f"(c[0]), "+f"(c[1]), "+f"(c[2]), "+f"(c[3])
        : "r"(a[0]), "r"(a[1]), "r"(a[2]), "r"(a[3]), "r"(b[0]), "r"(b[1]));
}
__device__ __forceinline__ uint32_t pack_h2(float a, float b) {
    __half2 v = __floats2half2_rn(a, b);
    return *(uint32_t*)&v;
}

// ---------------------------------------------------------------------------
// fp32 -> bf16 hi/lo split
// ---------------------------------------------------------------------------
__global__ __launch_bounds__(256) void split_f32(const float* __restrict__ src,
                                                 __nv_bfloat16* __restrict__ h,
                                                 __nv_bfloat16* __restrict__ l,
                                                 int n4) {
    int i = blockIdx.x * 256 + threadIdx.x;
    if (i >= n4) return;
    float4 v = *(const float4*)&src[(size_t)i * 4];
    float vv[4] = {v.x, v.y, v.z, v.w};
    __nv_bfloat16 hh[4], ll[4];
    #pragma unroll
    for (int j = 0; j < 4; j++) {
        hh[j] = __float2bfloat16(vv[j]);
        ll[j] = __float2bfloat16(vv[j] - __bfloat162float(hh[j]));
    }
    *(uint2*)&h[(size_t)i * 4] = *(uint2*)hh;
    *(uint2*)&l[(size_t)i * 4] = *(uint2*)ll;
}

// ---------------------------------------------------------------------------
// GEMM on bf16 planes:  C[M,N] = (Ah+Al)[M,K] @ (Bh+Bl)[N,K]^T  (3-pass split)
// 128x256 tile, BK=32, 512 threads; 3-stage cp.async pipeline.
// OUT_MODE: 0 = fp32, 2 = fp16 single plane.
// ---------------------------------------------------------------------------
#define G_ROW   80
#define G_AH    0
#define G_AL    10240
#define G_BH    20480
#define G_BL    40960
#define G_STAGE 61440
#define G_SMEM  (3*G_STAGE)

__device__ __forceinline__ void gemm_issue(uint32_t sb,
                                           const __nv_bfloat16* Ah, const __nv_bfloat16* Al,
                                           const __nv_bfloat16* Bh, const __nv_bfloat16* Bl,
                                           int row0, int col0, int k0, int K, int t) {
    {
        int r = t >> 2, s = t & 3;
        uint32_t d = sb + r * G_ROW + s * 16;
        size_t ga = (size_t)(row0 + r) * K + k0 + s * 8;
        cp16(d + G_AH, Ah + ga);
        cp16(d + G_AL, Al + ga);
    }
    #pragma unroll
    for (int p = 0; p < 2; p++) {
        int id = t + p * 512;
        int r = id >> 2, s = id & 3;
        uint32_t d = sb + r * G_ROW + s * 16;
        size_t gb = (size_t)(col0 + r) * K + k0 + s * 8;
        cp16(d + G_BH, Bh + gb);
        cp16(d + G_BL, Bl + gb);
    }
}

template<int OUT_MODE>
__global__ __launch_bounds__(512, 1) void gemm_planes(const __nv_bfloat16* __restrict__ Ah,
                                                      const __nv_bfloat16* __restrict__ Al,
                                                      const __nv_bfloat16* __restrict__ Bh,
                                                      const __nv_bfloat16* __restrict__ Bl,
                                                      float* __restrict__ Cf,
                                                      __half* __restrict__ Ch16,
                                                      int M, int N, int K) {
    extern __shared__ __align__(16) char dyn[];
    const uint32_t sbase = smem_u32(dyn);

    const int t    = threadIdx.x;
    const int lane = t & 31;
    const int wid  = t >> 5;
    const int wm   = (wid >> 2) * 32;
    const int wn   = (wid & 3) * 64;
    const int row0 = blockIdx.y * 128;
    const int col0 = blockIdx.x * 256;
    const int lrow = lane & 15;
    const int lkof = (lane >> 4) << 3;

    float acc[2][8][4];
    #pragma unroll
    for (int i = 0; i < 2; i++)
        #pragma unroll
        for (int j = 0; j < 8; j++)
            #pragma unroll
            for (int q = 0; q < 4; q++) acc[i][j][q] = 0.f;

    const int nchunk = K / 32;

    gemm_issue(sbase, Ah, Al, Bh, Bl, row0, col0, 0, K, t);
    CP_COMMIT();
    gemm_issue(sbase + G_STAGE, Ah, Al, Bh, Bl, row0, col0, 32, K, t);
    CP_COMMIT();

    int stage = 0;
    for (int ch = 0; ch < nchunk; ++ch) {
        if (ch + 1 < nchunk) { CP_WAIT1(); } else { CP_WAIT0(); }
        __syncthreads();
        if (ch + 2 < nchunk) {
            int ns = stage + 2; if (ns >= 3) ns -= 3;
            gemm_issue(sbase + ns * G_STAGE, Ah, Al, Bh, Bl,
                       row0, col0, (ch + 2) * 32, K, t);
            CP_COMMIT();
        }
        const uint32_t sb = sbase + stage * G_STAGE;
        if (++stage == 3) stage = 0;

        #pragma unroll
        for (int ks = 0; ks < 2; ks++) {
            const int kb = ks * 16 + lkof;

            uint32_t ah[2][4], al[2][4];
            #pragma unroll
            for (int mf = 0; mf < 2; mf++) {
                uint32_t aoff = (uint32_t)((wm + mf * 16 + lrow) * G_ROW + kb * 2);
                ldm_x4(ah[mf], sb + G_AH + aoff);
                ldm_x4(al[mf], sb + G_AL + aoff);
            }
            #pragma unroll
            for (int nn = 0; nn < 4; nn++) {
                uint32_t boff = (uint32_t)((wn + nn * 16 + lrow) * G_ROW + kb * 2);
                uint32_t rh[4], rl[4];
                ldm_x4(rh, sb + G_BH + boff);
                ldm_x4(rl, sb + G_BL + boff);
                uint32_t b0h[2] = {rh[0], rh[2]};
                uint32_t b1h[2] = {rh[1], rh[3]};
                uint32_t b0l[2] = {rl[0], rl[2]};
                uint32_t b1l[2] = {rl[1], rl[3]};
                #pragma unroll
                for (int mf = 0; mf < 2; mf++) {
                    mma_bf16(acc[mf][2*nn],   ah[mf], b0h);
                    mma_bf16(acc[mf][2*nn],   ah[mf], b0l);
                    mma_bf16(acc[mf][2*nn],   al[mf], b0h);
                    mma_bf16(acc[mf][2*nn+1], ah[mf], b1h);
                    mma_bf16(acc[mf][2*nn+1], ah[mf], b1l);
                    mma_bf16(acc[mf][2*nn+1], al[mf], b1h);
                }
            }
        }
    }

    #pragma unroll
    for (int mf = 0; mf < 2; mf++) {
        const int row = row0 + wm + mf * 16 + (lane >> 2);
        #pragma unroll
        for (int nf = 0; nf < 8; nf++) {
            const int col = col0 + wn + nf * 8 + (lane & 3) * 2;
            if (OUT_MODE == 2) {
                #pragma unroll
                for (int half_ = 0; half_ < 2; half_++) {
                    const size_t o = (size_t)(row + half_ * 8) * N + col;
                    __half2 hv = __floats2half2_rn(acc[mf][nf][2*half_],
                                                   acc[mf][nf][2*half_ + 1]);
                    *(__half2*)&Ch16[o] = hv;
                }
            } else {
                *(float2*)&Cf[(size_t)row * N + col] =
                    make_float2(acc[mf][nf][0], acc[mf][nf][1]);
                *(float2*)&Cf[(size_t)(row + 8) * N + col] =
                    make_float2(acc[mf][nf][2], acc[mf][nf][3]);
            }
        }
    }
}

// ---------------------------------------------------------------------------
// Flash attention, causal, single-pass fp16 mma, cp.async double-buffered K/V.
// CTA: 128 queries x (head,batch); 8 warps; 16 q-rows/warp; register softmax.
// Writes bf16 hi/lo planes for the (exact-path) proj GEMM.
// ---------------------------------------------------------------------------
#define A_ROW   144                     // 64 fp16 (128B) + 16B pad
#define A_K     0
#define A_V     9216
#define A_STAGE 18432
#define A_SMEM  (2*A_STAGE)

__device__ __forceinline__ void attn_issue(uint32_t sb, const __half* qf,
                                           size_t base, int k0, int kcol, int vcol, int t) {
    #pragma unroll
    for (int p = 0; p < 2; p++) {
        int id = t + p * 256;
        int r = id >> 3, s = id & 7;
        size_t gk = base + (size_t)(k0 + r) * QKV_STRIDE + kcol + s * 8;
        size_t gv = base + (size_t)(k0 + r) * QKV_STRIDE + vcol + s * 8;
        uint32_t d = sb + r * A_ROW + s * 16;
        cp16(d + A_K, qf + gk);
        cp16(d + A_V, qf + gv);
    }
}

__global__ __launch_bounds__(256) void attn_mma(const __half* __restrict__ qf16,
                                                __nv_bfloat16* __restrict__ oh,
                                                __nv_bfloat16* __restrict__ ol) {
    extern __shared__ __align__(16) char dyn[];
    const uint32_t sbase = smem_u32(dyn);

    const int t    = threadIdx.x;
    const int lane = t & 31;
    const int w    = t >> 5;
    const int q0   = (gridDim.x - 1 - blockIdx.x) * 128;   // heavy blocks first
    const int h    = blockIdx.y;
    const int b    = blockIdx.z;
    const size_t base = (size_t)b * T_ * QKV_STRIDE;
    const int qcol = h * HD;
    const int kcol = C_ + h * HD;
    const int vcol = 2 * C_ + h * HD;
    const int lrow = lane & 15;
    const int lkof = (lane >> 4) << 3;

    // ---- stage Q (128x64 fp16) into stage 0, frag to regs ----
    #pragma unroll
    for (int p = 0; p < 4; p++) {
        int id = t + p * 256;
        int r = id >> 3, s = id & 7;
        size_t g = base + (size_t)(q0 + r) * QKV_STRIDE + qcol + s * 8;
        uint32_t d = sbase + (r < 64 ? A_K + r * A_ROW : A_V + (r - 64) * A_ROW) + s * 16;
        cp16(d, qf16 + g);
    }
    CP_COMMIT();
    CP_WAIT0();
    __syncthreads();

    uint32_t qf[4][4];
    {
        const uint32_t bq = sbase + (w < 4 ? A_K : A_V);
        const uint32_t rofs = (uint32_t)(((w & 3) * 16 + lrow) * A_ROW);
        #pragma unroll
        for (int ks = 0; ks < 4; ks++) {
            uint32_t co = (uint32_t)((ks * 16 + lkof) * 2);
            ldm_x4(qf[ks], bq + rofs + co);
        }
    }
    __syncthreads();

    float mA = -1e30f, mB = -1e30f, lA = 0.f, lB = 0.f;
    float oacc[8][4];
    #pragma unroll
    for (int i = 0; i < 8; i++)
        #pragma unroll
        for (int j = 0; j < 4; j++) oacc[i][j] = 0.f;

    const int rowA = q0 + w * 16 + (lane >> 2);
    const int rowmax = q0 + w * 16 + 15;
    const int ntiles = q0 / 64 + 2;

    attn_issue(sbase, qf16, base, 0, kcol, vcol, t);
    CP_COMMIT();

    for (int kt = 0; kt < ntiles; kt++) {
        const int k0 = kt * 64;
        CP_WAIT0();
        __syncthreads();
        if (kt + 1 < ntiles) {
            attn_issue(sbase + ((kt + 1) & 1) * A_STAGE, qf16, base,
                       (kt + 1) * 64, kcol, vcol, t);
            CP_COMMIT();
        }
        const uint32_t sb = sbase + (kt & 1) * A_STAGE;

        if (k0 <= rowmax) {
            // ---- S = Q K^T (single pass fp16) ----
            float sacc[8][4];
            #pragma unroll
            for (int i = 0; i < 8; i++)
                #pragma unroll
                for (int j = 0; j < 4; j++) sacc[i][j] = 0.f;

            #pragma unroll
            for (int ks = 0; ks < 4; ks++) {
                const uint32_t co = (uint32_t)((ks * 16 + lkof) * 2);
                #pragma unroll
                for (int nn = 0; nn < 4; nn++) {
                    uint32_t ro = (uint32_t)((nn * 16 + lrow) * A_ROW);
                    uint32_t rh[4];
                    ldm_x4(rh, sb + A_K + ro + co);
                    uint32_t k0f[2] = {rh[0], rh[2]};
                    uint32_t k1f[2] = {rh[1], rh[3]};
                    mma_f16(sacc[2*nn],   qf[ks], k0f);
                    mma_f16(sacc[2*nn+1], qf[ks], k1f);
                }
            }

            // ---- scale + causal mask ----
            const bool need_mask = (k0 + 63 > q0 + w * 16);
            #pragma unroll
            for (int nf = 0; nf < 8; nf++) {
                #pragma unroll
                for (int j = 0; j < 4; j++) sacc[nf][j] *= 0.125f;
                if (need_mask) {
                    const int col = k0 + nf * 8 + (lane & 3) * 2;
                    if (col     > rowA)     sacc[nf][0] = -1e30f;
                    if (col + 1 > rowA)     sacc[nf][1] = -1e30f;
                    if (col     > rowA + 8) sacc[nf][2] = -1e30f;
                    if (col + 1 > rowA + 8) sacc[nf][3] = -1e30f;
                }
            }

            // ---- online softmax ----
            float tmA = -1e30f, tmB = -1e30f;
            #pragma unroll
            for (int nf = 0; nf < 8; nf++) {
                tmA = fmaxf(tmA, fmaxf(sacc[nf][0], sacc[nf][1]));
                tmB = fmaxf(tmB, fmaxf(sacc[nf][2], sacc[nf][3]));
            }
            tmA = fmaxf(tmA, __shfl_xor_sync(0xffffffffu, tmA, 1));
            tmA = fmaxf(tmA, __shfl_xor_sync(0xffffffffu, tmA, 2));
            tmB = fmaxf(tmB, __shfl_xor_sync(0xffffffffu, tmB, 1));
            tmB = fmaxf(tmB, __shfl_xor_sync(0xffffffffu, tmB, 2));

            const float mnA = fmaxf(mA, tmA);
            const float mnB = fmaxf(mB, tmB);
            const float aA = __expf(mA - mnA);
            const float aB = __expf(mB - mnB);

            float sumA = 0.f, sumB = 0.f;
            #pragma unroll
            for (int nf = 0; nf < 8; nf++) {
                sacc[nf][0] = __expf(sacc[nf][0] - mnA);
                sacc[nf][1] = __expf(sacc[nf][1] - mnA);
                sacc[nf][2] = __expf(sacc[nf][2] - mnB);
                sacc[nf][3] = __expf(sacc[nf][3] - mnB);
                sumA += sacc[nf][0] + sacc[nf][1];
                sumB += sacc[nf][2] + sacc[nf][3];
            }
            sumA += __shfl_xor_sync(0xffffffffu, sumA, 1);
            sumA += __shfl_xor_sync(0xffffffffu, sumA, 2);
            sumB += __shfl_xor_sync(0xffffffffu, sumB, 1);
            sumB += __shfl_xor_sync(0xffffffffu, sumB, 2);

            lA = lA * aA + sumA;  mA = mnA;
            lB = lB * aB + sumB;  mB = mnB;

            #pragma unroll
            for (int nf = 0; nf < 8; nf++) {
                oacc[nf][0] *= aA; oacc[nf][1] *= aA;
                oacc[nf][2] *= aB; oacc[nf][3] *= aB;
            }

            // ---- O += P V (single pass fp16) ----
            #pragma unroll
            for (int ks = 0; ks < 4; ks++) {
                uint32_t ph[4];
                ph[0] = pack_h2(sacc[2*ks][0],   sacc[2*ks][1]);
                ph[1] = pack_h2(sacc[2*ks][2],   sacc[2*ks][3]);
                ph[2] = pack_h2(sacc[2*ks+1][0], sacc[2*ks+1][1]);
                ph[3] = pack_h2(sacc[2*ks+1][2], sacc[2*ks+1][3]);

                const uint32_t krofs = (uint32_t)((ks * 16 + lrow) * A_ROW);
                #pragma unroll
                for (int nn = 0; nn < 4; nn++) {
                    uint32_t co = (uint32_t)((nn * 16 + lkof) * 2);
                    uint32_t vf[4];
                    ldm_x4_t(vf, sb + A_V + krofs + co);
                    uint32_t b0[2] = {vf[0], vf[1]};
                    uint32_t b1[2] = {vf[2], vf[3]};
                    mma_f16(oacc[2*nn],   ph, b0);
                    mma_f16(oacc[2*nn+1], ph, b1);
                }
            }
        }
    }

    // ---- epilogue: normalize, write bf16 hi/lo planes ----
    const float invA = 1.f / lA;
    const float invB = 1.f / lB;
    const size_t orowA = ((size_t)b * T_ + rowA) * C_ + h * HD;
    #pragma unroll
    for (int nf = 0; nf < 8; nf++) {
        const int col = nf * 8 + (lane & 3) * 2;
        #pragma unroll
        for (int half_ = 0; half_ < 2; half_++) {
            const size_t o = orowA + half_ * 8 * C_ + col;
            float v0 = oacc[nf][2*half_]     * (half_ ? invB : invA);
            float v1 = oacc[nf][2*half_ + 1] * (half_ ? invB : invA);
            __nv_bfloat16 h0 = __float2bfloat16(v0);
            __nv_bfloat16 h1 = __float2bfloat16(v1);
            __nv_bfloat162 hp; hp.x = h0; hp.y = h1;
            __nv_bfloat162 lp;
            lp.x = __float2bfloat16(v0 - __bfloat162float(h0));
            lp.y = __float2bfloat16(v1 - __bfloat162float(h1));
            *(__nv_bfloat162*)&oh[o] = hp;
            *(__nv_bfloat162*)&ol[o] = lp;
        }
    }
}

// ===========================================================================
extern "C" void kernel_launch(void* const* d_in, const int* in_sizes, int n_in,
                              void* d_out, int out_size) {
    const float* x      = (const float*)d_in[0];   // [B,T,C]
    const float* W_attn = (const float*)d_in[1];   // [3C,C]
    const float* W_proj = (const float*)d_in[2];   // [C,C]
    float* out = (float*)d_out;                    // [B,T,C]

    __nv_bfloat16 *xh, *xl, *wah, *wal, *wph, *wpl, *ah, *al;
    __half *qf;
    cudaGetSymbolAddress((void**)&xh,  g_xh);  cudaGetSymbolAddress((void**)&xl,  g_xl);
    cudaGetSymbolAddress((void**)&wah, g_wah); cudaGetSymbolAddress((void**)&wal, g_wal);
    cudaGetSymbolAddress((void**)&wph, g_wph); cudaGetSymbolAddress((void**)&wpl, g_wpl);
    cudaGetSymbolAddress((void**)&qf,  g_qf);
    cudaGetSymbolAddress((void**)&ah,  g_ah);  cudaGetSymbolAddress((void**)&al,  g_al);

    cudaFuncSetAttribute(gemm_planes<2>, cudaFuncAttributeMaxDynamicSharedMemorySize, G_SMEM);
    cudaFuncSetAttribute(gemm_planes<0>, cudaFuncAttributeMaxDynamicSharedMemorySize, G_SMEM);
    cudaFuncSetAttribute(attn_mma,       cudaFuncAttributeMaxDynamicSharedMemorySize, A_SMEM);

    // 0) conversions
    {
        int n4;
        n4 = M_ * C_ / 4;      split_f32<<<(n4 + 255) / 256, 256>>>(x,      xh,  xl,  n4);
        n4 = 3 * C_ * C_ / 4;  split_f32<<<(n4 + 255) / 256, 256>>>(W_attn, wah, wal, n4);
        n4 = C_ * C_ / 4;      split_f32<<<(n4 + 255) / 256, 256>>>(W_proj, wph, wpl, n4);
    }

    // 1) qkv = x @ W_attn^T  -> fp16 single plane   [4096 x 2304]
    gemm_planes<2><<<dim3((3*C_)/256, M_/128), 512, G_SMEM>>>(
        xh, xl, wah, wal, nullptr, qf, M_, 3*C_, C_);

    // 2) causal attention (fp16 single pass) -> bf16 hi/lo planes
    attn_mma<<<dim3(T_/128, NH, B_), 256, A_SMEM>>>(qf, ah, al);

    // 3) out = attn @ W_proj^T -> fp32   [4096 x 768]
    gemm_planes<0><<<dim3(C_/256, M_/128), 512, G_SMEM>>>(
        ah, al, wph, wpl, out, nullptr, M_, C_, C_);
}

// round 10
// speedup vs baseline: 4.4288x; 1.2609x over previous
#include <cuda_runtime.h>
#include <cuda_bf16.h>
#include <cuda_fp16.h>
#include <cstdint>
#include <math.h>

#define B_  2
#define T_  2048
#define C_  768
#define NH  12
#define HD  64
#define QKV_STRIDE (3*C_)
#define M_  (B_*T_)          // 4096

// ---------------------------------------------------------------------------
// Scratch (allocation-free rule: __device__ globals).
// ---------------------------------------------------------------------------
__device__ __half g_xh [(size_t)M_*C_];     // x hi (fp16)
__device__ __half g_xl [(size_t)M_*C_];     // x lo (fp16 residual)
__device__ __half g_wa [(size_t)3*C_*C_];   // W_attn fp16
__device__ __half g_wp [(size_t)C_*C_];     // W_proj fp16
__device__ __half g_qf [(size_t)M_*3*C_];   // qkv fp16
__device__ __half g_ah [(size_t)M_*C_];     // attn out hi (fp16)
__device__ __half g_al [(size_t)M_*C_];     // attn out lo (fp16)

// ---------------------------------------------------------------------------
// helpers
// ---------------------------------------------------------------------------
__device__ __forceinline__ uint32_t smem_u32(const void* p) {
    uint32_t a;
    asm("{ .reg .u64 t; cvta.to.shared.u64 t, %1; cvt.u32.u64 %0, t; }"
        : "=r"(a) : "l"(p));
    return a;
}
__device__ __forceinline__ void cp16(uint32_t dst, const void* src) {
    asm volatile("cp.async.cg.shared.global [%0], [%1], 16;" :: "r"(dst), "l"(src));
}
#define CP_COMMIT() asm volatile("cp.async.commit_group;" ::: "memory")
#define CP_WAIT0()  asm volatile("cp.async.wait_group 0;" ::: "memory")
#define CP_WAIT1()  asm volatile("cp.async.wait_group 1;" ::: "memory")

__device__ __forceinline__ void ldm_x4(uint32_t* r, uint32_t addr) {
    asm volatile("ldmatrix.sync.aligned.m8n8.x4.shared.b16 {%0,%1,%2,%3}, [%4];"
                 : "=r"(r[0]), "=r"(r[1]), "=r"(r[2]), "=r"(r[3]) : "r"(addr));
}
__device__ __forceinline__ void ldm_x4_t(uint32_t* r, uint32_t addr) {
    asm volatile("ldmatrix.sync.aligned.m8n8.x4.trans.shared.b16 {%0,%1,%2,%3}, [%4];"
                 : "=r"(r[0]), "=r"(r[1]), "=r"(r[2]), "=r"(r[3]) : "r"(addr));
}
__device__ __forceinline__ void mma_f16(float* c, const uint32_t* a, const uint32_t* b) {
    asm volatile(
        "mma.sync.aligned.m16n8k16.row.col.f32.f16.f16.f32 "
        "{%0,%1,%2,%3}, {%4,%5,%6,%7}, {%8,%9}, {%0,%1,%2,%3};"
        : "+f"(c[0]), "+f"(c[1]), "+f"(c[2]), "+f"(c[3])
        : "r"(a[0]), "r"(a[1]), "r"(a[2]), "r"(a[3]), "r"(b[0]), "r"(b[1]));
}
__device__ __forceinline__ uint32_t pack_h2(float a, float b) {
    __half2 v = __floats2half2_rn(a, b);
    return *(uint32_t*)&v;
}

// ---------------------------------------------------------------------------
// conversion kernels
// ---------------------------------------------------------------------------
__global__ __launch_bounds__(256) void split_f32_h(const float* __restrict__ src,
                                                   __half* __restrict__ h,
                                                   __half* __restrict__ l,
                                                   int n4) {
    int i = blockIdx.x * 256 + threadIdx.x;
    if (i >= n4) return;
    float4 v = *(const float4*)&src[(size_t)i * 4];
    float vv[4] = {v.x, v.y, v.z, v.w};
    __half hh[4], ll[4];
    #pragma unroll
    for (int j = 0; j < 4; j++) {
        hh[j] = __float2half_rn(vv[j]);
        ll[j] = __float2half_rn(vv[j] - __half2float(hh[j]));
    }
    *(uint2*)&h[(size_t)i * 4] = *(uint2*)hh;
    *(uint2*)&l[(size_t)i * 4] = *(uint2*)ll;
}

__global__ __launch_bounds__(256) void conv_f32_h(const float* __restrict__ src,
                                                  __half* __restrict__ h, int n4) {
    int i = blockIdx.x * 256 + threadIdx.x;
    if (i >= n4) return;
    float4 v = *(const float4*)&src[(size_t)i * 4];
    __half hh[4] = {__float2half_rn(v.x), __float2half_rn(v.y),
                    __float2half_rn(v.z), __float2half_rn(v.w)};
    *(uint2*)&h[(size_t)i * 4] = *(uint2*)hh;
}

// ---------------------------------------------------------------------------
// GEMM:  C[M,N] = (Ah+Al)[M,K] @ B[N,K]^T    (2-pass fp16; B single plane)
// 128x256 tile, BK=32, 512 threads; 3-stage cp.async pipeline (120 KB smem).
// OUT_MODE: 0 = fp32, 2 = fp16 single plane.
// ---------------------------------------------------------------------------
#define G_ROW   80
#define G_AH    0
#define G_AL    10240
#define G_B     20480
#define G_STAGE 40960
#define G_SMEM  (3*G_STAGE)

__device__ __forceinline__ void gemm_issue(uint32_t sb,
                                           const __half* Ah, const __half* Al,
                                           const __half* Bf,
                                           int row0, int col0, int k0, int K, int t) {
    {
        int r = t >> 2, s = t & 3;
        uint32_t d = sb + r * G_ROW + s * 16;
        size_t ga = (size_t)(row0 + r) * K + k0 + s * 8;
        cp16(d + G_AH, Ah + ga);
        cp16(d + G_AL, Al + ga);
    }
    #pragma unroll
    for (int p = 0; p < 2; p++) {
        int id = t + p * 512;
        int r = id >> 2, s = id & 3;
        uint32_t d = sb + r * G_ROW + s * 16;
        size_t gb = (size_t)(col0 + r) * K + k0 + s * 8;
        cp16(d + G_B, Bf + gb);
    }
}

template<int OUT_MODE>
__global__ __launch_bounds__(512, 1) void gemm_f16(const __half* __restrict__ Ah,
                                                   const __half* __restrict__ Al,
                                                   const __half* __restrict__ Bf,
                                                   float* __restrict__ Cf,
                                                   __half* __restrict__ Ch16,
                                                   int M, int N, int K) {
    extern __shared__ __align__(16) char dyn[];
    const uint32_t sbase = smem_u32(dyn);

    const int t    = threadIdx.x;
    const int lane = t & 31;
    const int wid  = t >> 5;
    const int wm   = (wid >> 2) * 32;
    const int wn   = (wid & 3) * 64;
    const int row0 = blockIdx.y * 128;
    const int col0 = blockIdx.x * 256;
    const int lrow = lane & 15;
    const int lkof = (lane >> 4) << 3;

    float acc[2][8][4];
    #pragma unroll
    for (int i = 0; i < 2; i++)
        #pragma unroll
        for (int j = 0; j < 8; j++)
            #pragma unroll
            for (int q = 0; q < 4; q++) acc[i][j][q] = 0.f;

    const int nchunk = K / 32;   // 24

    // prologue: issue chunks 0,1 into stages 0,1
    gemm_issue(sbase, Ah, Al, Bf, row0, col0, 0, K, t);
    CP_COMMIT();
    gemm_issue(sbase + G_STAGE, Ah, Al, Bf, row0, col0, 32, K, t);
    CP_COMMIT();

    int stage = 0;
    for (int ch = 0; ch < nchunk; ++ch) {
        if (ch + 1 < nchunk) { CP_WAIT1(); } else { CP_WAIT0(); }
        __syncthreads();
        if (ch + 2 < nchunk) {
            int ns = stage + 2; if (ns >= 3) ns -= 3;
            gemm_issue(sbase + ns * G_STAGE, Ah, Al, Bf,
                       row0, col0, (ch + 2) * 32, K, t);
            CP_COMMIT();
        }
        const uint32_t sb = sbase + stage * G_STAGE;
        if (++stage == 3) stage = 0;

        #pragma unroll
        for (int ks = 0; ks < 2; ks++) {
            const int kb = ks * 16 + lkof;

            uint32_t ah[2][4], al[2][4];
            #pragma unroll
            for (int mf = 0; mf < 2; mf++) {
                uint32_t aoff = (uint32_t)((wm + mf * 16 + lrow) * G_ROW + kb * 2);
                ldm_x4(ah[mf], sb + G_AH + aoff);
                ldm_x4(al[mf], sb + G_AL + aoff);
            }
            #pragma unroll
            for (int nn = 0; nn < 4; nn++) {
                uint32_t boff = (uint32_t)((wn + nn * 16 + lrow) * G_ROW + kb * 2);
                uint32_t rb[4];
                ldm_x4(rb, sb + G_B + boff);
                uint32_t b0[2] = {rb[0], rb[2]};
                uint32_t b1[2] = {rb[1], rb[3]};
                #pragma unroll
                for (int mf = 0; mf < 2; mf++) {
                    mma_f16(acc[mf][2*nn],   ah[mf], b0);
                    mma_f16(acc[mf][2*nn],   al[mf], b0);
                    mma_f16(acc[mf][2*nn+1], ah[mf], b1);
                    mma_f16(acc[mf][2*nn+1], al[mf], b1);
                }
            }
        }
        // no bottom barrier: this stage is rewritten only after the next
        // iteration's top barrier (all warps done reading it).
    }

    #pragma unroll
    for (int mf = 0; mf < 2; mf++) {
        const int row = row0 + wm + mf * 16 + (lane >> 2);
        #pragma unroll
        for (int nf = 0; nf < 8; nf++) {
            const int col = col0 + wn + nf * 8 + (lane & 3) * 2;
            if (OUT_MODE == 2) {
                #pragma unroll
                for (int half_ = 0; half_ < 2; half_++) {
                    const size_t o = (size_t)(row + half_ * 8) * N + col;
                    __half2 hv = __floats2half2_rn(acc[mf][nf][2*half_],
                                                   acc[mf][nf][2*half_ + 1]);
                    *(__half2*)&Ch16[o] = hv;
                }
            } else {
                *(float2*)&Cf[(size_t)row * N + col] =
                    make_float2(acc[mf][nf][0], acc[mf][nf][1]);
                *(float2*)&Cf[(size_t)(row + 8) * N + col] =
                    make_float2(acc[mf][nf][2], acc[mf][nf][3]);
            }
        }
    }
}

// ---------------------------------------------------------------------------
// Flash attention, causal, single-pass fp16 mma, cp.async double-buffered K/V.
// CTA: 128 queries x (head,batch); 8 warps; 16 q-rows/warp; register softmax.
// Writes fp16 hi/lo planes (exact) for the proj GEMM.
// ---------------------------------------------------------------------------
#define A_ROW   144
#define A_K     0
#define A_V     9216
#define A_STAGE 18432
#define A_SMEM  (2*A_STAGE)

__device__ __forceinline__ void attn_issue(uint32_t sb, const __half* qf,
                                           size_t base, int k0, int kcol, int vcol, int t) {
    #pragma unroll
    for (int p = 0; p < 2; p++) {
        int id = t + p * 256;
        int r = id >> 3, s = id & 7;
        size_t gk = base + (size_t)(k0 + r) * QKV_STRIDE + kcol + s * 8;
        size_t gv = base + (size_t)(k0 + r) * QKV_STRIDE + vcol + s * 8;
        uint32_t d = sb + r * A_ROW + s * 16;
        cp16(d + A_K, qf + gk);
        cp16(d + A_V, qf + gv);
    }
}

__global__ __launch_bounds__(256) void attn_mma(const __half* __restrict__ qf16,
                                                __half* __restrict__ oh,
                                                __half* __restrict__ ol) {
    extern __shared__ __align__(16) char dyn[];
    const uint32_t sbase = smem_u32(dyn);

    const int t    = threadIdx.x;
    const int lane = t & 31;
    const int w    = t >> 5;
    const int q0   = (gridDim.x - 1 - blockIdx.x) * 128;   // heavy blocks first
    const int h    = blockIdx.y;
    const int b    = blockIdx.z;
    const size_t base = (size_t)b * T_ * QKV_STRIDE;
    const int qcol = h * HD;
    const int kcol = C_ + h * HD;
    const int vcol = 2 * C_ + h * HD;
    const int lrow = lane & 15;
    const int lkof = (lane >> 4) << 3;

    // ---- stage Q (128x64 fp16) into stage 0, frag to regs ----
    #pragma unroll
    for (int p = 0; p < 4; p++) {
        int id = t + p * 256;
        int r = id >> 3, s = id & 7;
        size_t g = base + (size_t)(q0 + r) * QKV_STRIDE + qcol + s * 8;
        uint32_t d = sbase + (r < 64 ? A_K + r * A_ROW : A_V + (r - 64) * A_ROW) + s * 16;
        cp16(d, qf16 + g);
    }
    CP_COMMIT();
    CP_WAIT0();
    __syncthreads();

    uint32_t qf[4][4];
    {
        const uint32_t bq = sbase + (w < 4 ? A_K : A_V);
        const uint32_t rofs = (uint32_t)(((w & 3) * 16 + lrow) * A_ROW);
        #pragma unroll
        for (int ks = 0; ks < 4; ks++) {
            uint32_t co = (uint32_t)((ks * 16 + lkof) * 2);
            ldm_x4(qf[ks], bq + rofs + co);
        }
    }
    __syncthreads();

    float mA = -1e30f, mB = -1e30f, lA = 0.f, lB = 0.f;
    float oacc[8][4];
    #pragma unroll
    for (int i = 0; i < 8; i++)
        #pragma unroll
        for (int j = 0; j < 4; j++) oacc[i][j] = 0.f;

    const int rowA = q0 + w * 16 + (lane >> 2);
    const int rowmax = q0 + w * 16 + 15;
    const int ntiles = q0 / 64 + 2;

    attn_issue(sbase, qf16, base, 0, kcol, vcol, t);
    CP_COMMIT();

    for (int kt = 0; kt < ntiles; kt++) {
        const int k0 = kt * 64;
        CP_WAIT0();
        __syncthreads();
        if (kt + 1 < ntiles) {
            attn_issue(sbase + ((kt + 1) & 1) * A_STAGE, qf16, base,
                       (kt + 1) * 64, kcol, vcol, t);
            CP_COMMIT();
        }
        const uint32_t sb = sbase + (kt & 1) * A_STAGE;

        if (k0 <= rowmax) {
            // ---- S = Q K^T ----
            float sacc[8][4];
            #pragma unroll
            for (int i = 0; i < 8; i++)
                #pragma unroll
                for (int j = 0; j < 4; j++) sacc[i][j] = 0.f;

            #pragma unroll
            for (int ks = 0; ks < 4; ks++) {
                const uint32_t co = (uint32_t)((ks * 16 + lkof) * 2);
                #pragma unroll
                for (int nn = 0; nn < 4; nn++) {
                    uint32_t ro = (uint32_t)((nn * 16 + lrow) * A_ROW);
                    uint32_t rh[4];
                    ldm_x4(rh, sb + A_K + ro + co);
                    uint32_t k0f[2] = {rh[0], rh[2]};
                    uint32_t k1f[2] = {rh[1], rh[3]};
                    mma_f16(sacc[2*nn],   qf[ks], k0f);
                    mma_f16(sacc[2*nn+1], qf[ks], k1f);
                }
            }

            // ---- scale + causal mask ----
            const bool need_mask = (k0 + 63 > q0 + w * 16);
            #pragma unroll
            for (int nf = 0; nf < 8; nf++) {
                #pragma unroll
                for (int j = 0; j < 4; j++) sacc[nf][j] *= 0.125f;
                if (need_mask) {
                    const int col = k0 + nf * 8 + (lane & 3) * 2;
                    if (col     > rowA)     sacc[nf][0] = -1e30f;
                    if (col + 1 > rowA)     sacc[nf][1] = -1e30f;
                    if (col     > rowA + 8) sacc[nf][2] = -1e30f;
                    if (col + 1 > rowA + 8) sacc[nf][3] = -1e30f;
                }
            }

            // ---- online softmax ----
            float tmA = -1e30f, tmB = -1e30f;
            #pragma unroll
            for (int nf = 0; nf < 8; nf++) {
                tmA = fmaxf(tmA, fmaxf(sacc[nf][0], sacc[nf][1]));
                tmB = fmaxf(tmB, fmaxf(sacc[nf][2], sacc[nf][3]));
            }
            tmA = fmaxf(tmA, __shfl_xor_sync(0xffffffffu, tmA, 1));
            tmA = fmaxf(tmA, __shfl_xor_sync(0xffffffffu, tmA, 2));
            tmB = fmaxf(tmB, __shfl_xor_sync(0xffffffffu, tmB, 1));
            tmB = fmaxf(tmB, __shfl_xor_sync(0xffffffffu, tmB, 2));

            const float mnA = fmaxf(mA, tmA);
            const float mnB = fmaxf(mB, tmB);
            const float aA = __expf(mA - mnA);
            const float aB = __expf(mB - mnB);

            float sumA = 0.f, sumB = 0.f;
            #pragma unroll
            for (int nf = 0; nf < 8; nf++) {
                sacc[nf][0] = __expf(sacc[nf][0] - mnA);
                sacc[nf][1] = __expf(sacc[nf][1] - mnA);
                sacc[nf][2] = __expf(sacc[nf][2] - mnB);
                sacc[nf][3] = __expf(sacc[nf][3] - mnB);
                sumA += sacc[nf][0] + sacc[nf][1];
                sumB += sacc[nf][2] + sacc[nf][3];
            }
            sumA += __shfl_xor_sync(0xffffffffu, sumA, 1);
            sumA += __shfl_xor_sync(0xffffffffu, sumA, 2);
            sumB += __shfl_xor_sync(0xffffffffu, sumB, 1);
            sumB += __shfl_xor_sync(0xffffffffu, sumB, 2);

            lA = lA * aA + sumA;  mA = mnA;
            lB = lB * aB + sumB;  mB = mnB;

            #pragma unroll
            for (int nf = 0; nf < 8; nf++) {
                oacc[nf][0] *= aA; oacc[nf][1] *= aA;
                oacc[nf][2] *= aB; oacc[nf][3] *= aB;
            }

            // ---- O += P V ----
            #pragma unroll
            for (int ks = 0; ks < 4; ks++) {
                uint32_t ph[4];
                ph[0] = pack_h2(sacc[2*ks][0],   sacc[2*ks][1]);
                ph[1] = pack_h2(sacc[2*ks][2],   sacc[2*ks][3]);
                ph[2] = pack_h2(sacc[2*ks+1][0], sacc[2*ks+1][1]);
                ph[3] = pack_h2(sacc[2*ks+1][2], sacc[2*ks+1][3]);

                const uint32_t krofs = (uint32_t)((ks * 16 + lrow) * A_ROW);
                #pragma unroll
                for (int nn = 0; nn < 4; nn++) {
                    uint32_t co = (uint32_t)((nn * 16 + lkof) * 2);
                    uint32_t vf[4];
                    ldm_x4_t(vf, sb + A_V + krofs + co);
                    uint32_t b0[2] = {vf[0], vf[1]};
                    uint32_t b1[2] = {vf[2], vf[3]};
                    mma_f16(oacc[2*nn],   ph, b0);
                    mma_f16(oacc[2*nn+1], ph, b1);
                }
            }
        }
    }

    // ---- epilogue: normalize, write fp16 hi/lo planes ----
    const float invA = 1.f / lA;
    const float invB = 1.f / lB;
    const size_t orowA = ((size_t)b * T_ + rowA) * C_ + h * HD;
    #pragma unroll
    for (int nf = 0; nf < 8; nf++) {
        const int col = nf * 8 + (lane & 3) * 2;
        #pragma unroll
        for (int half_ = 0; half_ < 2; half_++) {
            const size_t o = orowA + half_ * 8 * C_ + col;
            float v0 = oacc[nf][2*half_]     * (half_ ? invB : invA);
            float v1 = oacc[nf][2*half_ + 1] * (half_ ? invB : invA);
            __half h0 = __float2half_rn(v0);
            __half h1 = __float2half_rn(v1);
            __half2 hp; hp.x = h0; hp.y = h1;
            __half2 lp;
            lp.x = __float2half_rn(v0 - __half2float(h0));
            lp.y = __float2half_rn(v1 - __half2float(h1));
            *(__half2*)&oh[o] = hp;
            *(__half2*)&ol[o] = lp;
        }
    }
}

// ===========================================================================
extern "C" void kernel_launch(void* const* d_in, const int* in_sizes, int n_in,
                              void* d_out, int out_size) {
    const float* x      = (const float*)d_in[0];   // [B,T,C]
    const float* W_attn = (const float*)d_in[1];   // [3C,C]
    const float* W_proj = (const float*)d_in[2];   // [C,C]
    float* out = (float*)d_out;                    // [B,T,C]

    __half *xh, *xl, *wa, *wp, *qf, *ah, *al;
    cudaGetSymbolAddress((void**)&xh, g_xh); cudaGetSymbolAddress((void**)&xl, g_xl);
    cudaGetSymbolAddress((void**)&wa, g_wa); cudaGetSymbolAddress((void**)&wp, g_wp);
    cudaGetSymbolAddress((void**)&qf, g_qf);
    cudaGetSymbolAddress((void**)&ah, g_ah); cudaGetSymbolAddress((void**)&al, g_al);

    cudaFuncSetAttribute(gemm_f16<2>, cudaFuncAttributeMaxDynamicSharedMemorySize, G_SMEM);
    cudaFuncSetAttribute(gemm_f16<0>, cudaFuncAttributeMaxDynamicSharedMemorySize, G_SMEM);
    cudaFuncSetAttribute(attn_mma,    cudaFuncAttributeMaxDynamicSharedMemorySize, A_SMEM);

    // 0) conversions
    {
        int n4;
        n4 = M_ * C_ / 4;      split_f32_h<<<(n4 + 255) / 256, 256>>>(x, xh, xl, n4);
        n4 = 3 * C_ * C_ / 4;  conv_f32_h<<<(n4 + 255) / 256, 256>>>(W_attn, wa, n4);
        n4 = C_ * C_ / 4;      conv_f32_h<<<(n4 + 255) / 256, 256>>>(W_proj, wp, n4);
    }

    // 1) qkv = x @ W_attn^T  -> fp16   [4096 x 2304]
    gemm_f16<2><<<dim3((3*C_)/256, M_/128), 512, G_SMEM>>>(
        xh, xl, wa, nullptr, qf, M_, 3*C_, C_);

    // 2) causal attention (fp16) -> fp16 hi/lo planes
    attn_mma<<<dim3(T_/128, NH, B_), 256, A_SMEM>>>(qf, ah, al);

    // 3) out = attn @ W_proj^T -> fp32   [4096 x 768]
    gemm_f16<0><<<dim3(C_/256, M_/128), 512, G_SMEM>>>(
        ah, al, wp, out, nullptr, M_, C_, C_);
}